// round 2
// baseline (speedup 1.0000x reference)
#include <cuda_runtime.h>
#include <cuda_bf16.h>
#include <math.h>
#include <stdint.h>

// Problem constants
#define B_    32
#define C_    256
#define H_    56
#define W_    56
#define HW_   3136
#define CHW_  802816      // 256*3136
#define TOT_  25690112    // 32*256*3136
#define NCH_  16          // chunks
#define QMAX_ 255.0f

#define FINF __int_as_float(0x7f800000)

// ---------------- device globals (scratch; no allocations allowed) ----------------
__device__ float h1_buf[TOT_];            // depthwise conv output (103 MB)

__device__ float g_x_smin[B_], g_x_smax[B_];
__device__ float g_h1_min[B_ * C_], g_h1_max[B_ * C_];   // per (s,c)
__device__ float g_h3_min[B_ * C_], g_h3_max[B_ * C_];   // per (s,o)
__device__ double g_sum1[C_], g_sum2[C_];
__device__ float g_pw_mn, g_pw_mx;

__device__ float g_mn[4], g_sc[4];        // 0:x 1:h1 2:h2 3:h3 quantizer params
__device__ float g_qdw[C_ * 9], g_qdwb[C_], g_qbn1w[C_], g_qbn2w[C_];
__device__ float g_qpwT[C_ * C_];         // quantized pointwise weights, [c][o] (transposed)
__device__ float g_A1[C_], g_C1[C_], g_A2[C_], g_C2[C_];

// ---------------- helpers ----------------
__device__ __forceinline__ float quantf(float v, float mn, float sc) {
    float t = (v - mn) / sc;
    t = fminf(fmaxf(t, 0.f), QMAX_);
    return rintf(t) * sc + mn;
}

__device__ __forceinline__ void atomicMaxF(float* a, float v) {
    if (v >= 0.f) atomicMax((int*)a, __float_as_int(v));
    else          atomicMin((unsigned int*)a, __float_as_uint(v));
}
__device__ __forceinline__ void atomicMinF(float* a, float v) {
    if (v >= 0.f) atomicMin((int*)a, __float_as_int(v));
    else          atomicMax((unsigned int*)a, __float_as_uint(v));
}

// blockDim.x == 256 assumed. sh must hold 512 floats.
__device__ float2 blockMinMax256(float lmn, float lmx, float* sh) {
    int t = threadIdx.x;
    __syncthreads();
    sh[t] = lmn; sh[256 + t] = lmx;
    __syncthreads();
    for (int o = 128; o > 0; o >>= 1) {
        if (t < o) {
            sh[t]       = fminf(sh[t], sh[t + o]);
            sh[256 + t] = fmaxf(sh[256 + t], sh[256 + t + o]);
        }
        __syncthreads();
    }
    float2 r = make_float2(sh[0], sh[256]);
    __syncthreads();
    return r;
}

// ---------------- kernels ----------------
__global__ void init_kernel() {
    int i = blockIdx.x * blockDim.x + threadIdx.x;
    if (i < B_ * C_) {
        g_h1_min[i] = FINF; g_h1_max[i] = -FINF;
        g_h3_min[i] = FINF; g_h3_max[i] = -FINF;
    }
    if (i < C_) { g_sum1[i] = 0.0; g_sum2[i] = 0.0; }
    if (i < B_) { g_x_smin[i] = FINF; g_x_smax[i] = -FINF; }
    if (i == 0) { g_pw_mn = FINF; g_pw_mx = -FINF; }
}

__global__ __launch_bounds__(256) void xminmax_kernel(const float* __restrict__ x) {
    __shared__ float sh[512];
    int s = blockIdx.y;
    const float* xp = x + (size_t)s * CHW_;
    float mn = FINF, mx = -FINF;
    for (int i = blockIdx.x * blockDim.x + threadIdx.x; i < CHW_; i += gridDim.x * blockDim.x) {
        float v = xp[i];
        mn = fminf(mn, v); mx = fmaxf(mx, v);
    }
    float2 r = blockMinMax256(mn, mx, sh);
    if (threadIdx.x == 0) { atomicMinF(&g_x_smin[s], r.x); atomicMaxF(&g_x_smax[s], r.y); }
}

__global__ __launch_bounds__(256) void pwminmax_kernel(const float* __restrict__ pw) {
    __shared__ float sh[512];
    float mn = FINF, mx = -FINF;
    for (int i = blockIdx.x * blockDim.x + threadIdx.x; i < C_ * C_; i += gridDim.x * blockDim.x) {
        float v = pw[i];
        mn = fminf(mn, v); mx = fmaxf(mx, v);
    }
    float2 r = blockMinMax256(mn, mx, sh);
    if (threadIdx.x == 0) { atomicMinF(&g_pw_mn, r.x); atomicMaxF(&g_pw_mx, r.y); }
}

__global__ __launch_bounds__(256) void prep1_kernel(const float* __restrict__ dw_w,
                                                    const float* __restrict__ dw_b,
                                                    const float* __restrict__ bn1_w,
                                                    const float* __restrict__ bn2_w) {
    __shared__ float sh[512];
    int t = threadIdx.x;
    if (t == 0) {
        float a = 0.f, b = 0.f;
        for (int s = 0; s < B_; s++) { a += g_x_smin[s]; b += g_x_smax[s]; }
        float mn = a / 32.f, mx = b / 32.f;
        g_mn[0] = mn;
        g_sc[0] = fmaxf((mx - mn) / QMAX_, 1e-8f);
    }
    // depthwise weights (2304)
    {
        float mn = FINF, mx = -FINF;
        for (int i = t; i < C_ * 9; i += 256) { float v = dw_w[i]; mn = fminf(mn, v); mx = fmaxf(mx, v); }
        float2 r = blockMinMax256(mn, mx, sh);
        float sc = fmaxf((r.y - r.x) / QMAX_, 1e-8f);
        for (int i = t; i < C_ * 9; i += 256) g_qdw[i] = quantf(dw_w[i], r.x, sc);
    }
    // depthwise bias (256)
    {
        float v = dw_b[t];
        float2 r = blockMinMax256(v, v, sh);
        float sc = fmaxf((r.y - r.x) / QMAX_, 1e-8f);
        g_qdwb[t] = quantf(v, r.x, sc);
    }
    // bn1_w (256)
    {
        float v = bn1_w[t];
        float2 r = blockMinMax256(v, v, sh);
        float sc = fmaxf((r.y - r.x) / QMAX_, 1e-8f);
        g_qbn1w[t] = quantf(v, r.x, sc);
    }
    // bn2_w (256)
    {
        float v = bn2_w[t];
        float2 r = blockMinMax256(v, v, sh);
        float sc = fmaxf((r.y - r.x) / QMAX_, 1e-8f);
        g_qbn2w[t] = quantf(v, r.x, sc);
    }
}

__global__ __launch_bounds__(256) void quantpw_kernel(const float* __restrict__ pw) {
    float mn = g_pw_mn, mx = g_pw_mx;
    float sc = fmaxf((mx - mn) / QMAX_, 1e-8f);
    int i = blockIdx.x * 256 + threadIdx.x;
    if (i < C_ * C_) {
        int o = i >> 8, c = i & 255;
        g_qpwT[c * C_ + o] = quantf(pw[i], mn, sc);   // transpose to [c][o]
    }
}

// Depthwise 3x3, pad 1. One block per (s,c) plane. Fused input quantization,
// quantized weights/bias, per-(s,c) min/max of output (exact, no atomics).
__global__ __launch_bounds__(256) void conv_kernel(const float* __restrict__ x) {
    int c = blockIdx.x, s = blockIdx.y;
    __shared__ float tile[58 * 58];
    __shared__ float sh[512];
    const float mn0 = g_mn[0], s0 = g_sc[0];
    const float* xp = x + ((size_t)s * C_ + c) * HW_;
    int t = threadIdx.x;
    for (int i = t; i < 58 * 58; i += 256) {
        int r = i / 58, q = i - r * 58;
        int gy = r - 1, gx = q - 1;
        float v = 0.f;  // zero padding is NOT quantized
        if ((unsigned)gy < 56u && (unsigned)gx < 56u) v = quantf(xp[gy * 56 + gx], mn0, s0);
        tile[i] = v;
    }
    float w[9];
#pragma unroll
    for (int k = 0; k < 9; k++) w[k] = g_qdw[c * 9 + k];
    float bias = g_qdwb[c];
    __syncthreads();
    float* hp = h1_buf + ((size_t)s * C_ + c) * HW_;
    float mn = FINF, mx = -FINF;
    for (int p = t; p < HW_; p += 256) {
        int yy = p / 56, xx = p - yy * 56;
        const float* tp = tile + yy * 58 + xx;
        float acc = bias;
        acc += tp[0] * w[0] + tp[1] * w[1] + tp[2] * w[2];
        acc += tp[58] * w[3] + tp[59] * w[4] + tp[60] * w[5];
        acc += tp[116] * w[6] + tp[117] * w[7] + tp[118] * w[8];
        hp[p] = acc;
        mn = fminf(mn, acc); mx = fmaxf(mx, acc);
    }
    float2 r = blockMinMax256(mn, mx, sh);
    if (t == 0) { g_h1_min[s * C_ + c] = r.x; g_h1_max[s * C_ + c] = r.y; }
}

// stage 0: h1 stats -> g_mn[1],g_sc[1], A1 ; stage 1: h3 stats -> g_mn[3],g_sc[3], A2
__global__ __launch_bounds__(256) void prep_stats_kernel(int stage) {
    int t = threadIdx.x;
    const float* MN  = stage ? g_h3_min : g_h1_min;
    const float* MX  = stage ? g_h3_max : g_h1_max;
    const float* QBW = stage ? g_qbn2w : g_qbn1w;
    float* A = stage ? g_A2 : g_A1;
    int qi = stage ? 3 : 1;

    __shared__ float smn[B_], smx[B_];
    __shared__ float s_mn, s_s;
    if (t < B_) {
        float mn = FINF, mx = -FINF;
        for (int c = 0; c < C_; c++) {
            mn = fminf(mn, MN[t * C_ + c]);
            mx = fmaxf(mx, MX[t * C_ + c]);
        }
        smn[t] = mn; smx[t] = mx;
    }
    __syncthreads();
    if (t == 0) {
        float a = 0.f, b = 0.f;
        for (int s = 0; s < B_; s++) { a += smn[s]; b += smx[s]; }
        float mn = a / 32.f, mx = b / 32.f;
        s_mn = mn;
        s_s = fmaxf((mx - mn) / QMAX_, 1e-8f);
        g_mn[qi] = s_mn; g_sc[qi] = s_s;
    }
    __syncthreads();
    float mn = s_mn, sv = s_s;

    // per-channel chunk stats; chunk j == samples {2j, 2j+1}; quantize is monotone
    float amax = 0.f, amin = 0.f;
    for (int j = 0; j < NCH_; j++) {
        float cmx = fmaxf(MX[(2 * j) * C_ + t], MX[(2 * j + 1) * C_ + t]);
        float cmn = fminf(MN[(2 * j) * C_ + t], MN[(2 * j + 1) * C_ + t]);
        amax += quantf(cmx, mn, sv);
        amin += quantf(cmn, mn, sv);
    }
    float mean_max = amax * (1.f / 16.f), mean_min = amin * (1.f / 16.f);
    double sfd = 0.175 * (1.0 + sqrt(3.141592653589793 * 1.3862943611198906))
               / sqrt(2.0 * log(6272.0));
    float sf = (float)sfd;
    float rs = 1.0f / ((mean_max - mean_min) * sf + 1e-5f);

    __shared__ float sh[512];
    float2 r = blockMinMax256(rs, rs, sh);
    float rsc = fmaxf((r.y - r.x) / QMAX_, 1e-8f);
    float qs = quantf(rs, r.x, rsc);
    A[t] = qs * QBW[t];
}

// per-channel sum of quantized values. src==0 -> h1_buf with q-params idx 1, else d_out with idx 3
__global__ __launch_bounds__(256) void qsum_kernel(const float* __restrict__ ext, int stage) {
    int c = blockIdx.x, s = blockIdx.y;
    float mn = g_mn[stage ? 3 : 1], sv = g_sc[stage ? 3 : 1];
    const float* hp = (stage ? ext : (const float*)h1_buf) + ((size_t)s * C_ + c) * HW_;
    double acc = 0.0;
    for (int p = threadIdx.x; p < HW_; p += 256) acc += (double)quantf(hp[p], mn, sv);
    __shared__ double sd[256];
    sd[threadIdx.x] = acc;
    __syncthreads();
    for (int o = 128; o > 0; o >>= 1) {
        if (threadIdx.x < o) sd[threadIdx.x] += sd[threadIdx.x + o];
        __syncthreads();
    }
    if (threadIdx.x == 0) atomicAdd(stage ? &g_sum2[c] : &g_sum1[c], sd[0]);
}

// stage 0: C1 from sum1 + derive h2 quantizer (mn2/s2). stage 1: C2 from sum2.
__global__ __launch_bounds__(256) void prep_mean_kernel(int stage, const float* __restrict__ bias) {
    int t = threadIdx.x;
    const double* SUM = stage ? g_sum2 : g_sum1;
    const float* A = stage ? g_A2 : g_A1;
    float* Cc = stage ? g_C2 : g_C1;
    float mean = (float)(SUM[t] * (1.0 / 100352.0));
    Cc[t] = bias[t] - mean * A[t];
    if (stage == 0) {
        __syncthreads();
        float mn1 = g_mn[1], s1 = g_sc[1];
        __shared__ float smn[B_], smx[B_];
        if (t < B_) {
            float lo = FINF, hi = -FINF;
            for (int c = 0; c < C_; c++) {
                float Aa = g_A1[c], Cv = g_C1[c];
                float v1 = Aa * quantf(g_h1_max[t * C_ + c], mn1, s1) + Cv;
                float v2 = Aa * quantf(g_h1_min[t * C_ + c], mn1, s1) + Cv;
                hi = fmaxf(hi, fmaxf(fmaxf(v1, v2), 0.f));
                lo = fminf(lo, fmaxf(fminf(v1, v2), 0.f));
            }
            smn[t] = lo; smx[t] = hi;
        }
        __syncthreads();
        if (t == 0) {
            float a = 0.f, b = 0.f;
            for (int s = 0; s < B_; s++) { a += smn[s]; b += smx[s]; }
            float mn2 = a / 32.f, mx2 = b / 32.f;
            g_mn[2] = mn2;
            g_sc[2] = fmaxf((mx2 - mn2) / QMAX_, 1e-8f);
        }
    }
}

// Pointwise 1x1 conv as tiled GEMM: per sample, out[o][p] = sum_c Wq[o][c] * f(h1[c][p]).
// f = quantize -> bn1 affine -> relu -> quantize (fused on load). Tracks per-(s,o) min/max.
#define BM 64
#define BN 64
#define BK 16
__global__ __launch_bounds__(256) void gemm_kernel(float* __restrict__ out) {
    int s = blockIdx.z;
    int om = blockIdx.y * BM;
    int pn = blockIdx.x * BN;
    const float mn1 = g_mn[1], s1 = g_sc[1];
    const float mn2 = g_mn[2], s2 = g_sc[2];

    __shared__ float As[BK][BM];   // [k][o]
    __shared__ float Bs[BK][BN];   // [k][p]
    int tid = threadIdx.x;
    int tx = tid & 15, ty = tid >> 4;
    float acc[4][4];
#pragma unroll
    for (int i = 0; i < 4; i++)
#pragma unroll
        for (int j = 0; j < 4; j++) acc[i][j] = 0.f;

    const float* h1s = h1_buf + (size_t)s * C_ * HW_;

    for (int k0 = 0; k0 < C_; k0 += BK) {
#pragma unroll
        for (int j = 0; j < 4; j++) {
            int e = tid + 256 * j;
            int m = e & 63, k = e >> 6;
            As[k][m] = g_qpwT[(k0 + k) * C_ + om + m];    // coalesced in m
        }
#pragma unroll
        for (int j = 0; j < 4; j++) {
            int e = tid + 256 * j;
            int p = e & 63, k = e >> 6;
            int c = k0 + k;
            float v = h1s[(size_t)c * HW_ + pn + p];
            float q1 = quantf(v, mn1, s1);
            float h2 = fmaxf(g_A1[c] * q1 + g_C1[c], 0.f);
            Bs[k][p] = quantf(h2, mn2, s2);
        }
        __syncthreads();
#pragma unroll
        for (int k = 0; k < BK; k++) {
            float4 av = *reinterpret_cast<const float4*>(&As[k][ty * 4]);
            float4 bv = *reinterpret_cast<const float4*>(&Bs[k][tx * 4]);
            float a[4] = {av.x, av.y, av.z, av.w};
            float b[4] = {bv.x, bv.y, bv.z, bv.w};
#pragma unroll
            for (int i = 0; i < 4; i++)
#pragma unroll
                for (int j = 0; j < 4; j++) acc[i][j] += a[i] * b[j];
        }
        __syncthreads();
    }

    // write + per-(s,o) min/max (shfl-reduce across the 16 tx lanes per o-row)
#pragma unroll
    for (int i = 0; i < 4; i++) {
        int o = om + ty * 4 + i;
        float4 v = make_float4(acc[i][0], acc[i][1], acc[i][2], acc[i][3]);
        *reinterpret_cast<float4*>(&out[((size_t)s * C_ + o) * HW_ + pn + tx * 4]) = v;
        float lmn = fminf(fminf(v.x, v.y), fminf(v.z, v.w));
        float lmx = fmaxf(fmaxf(v.x, v.y), fmaxf(v.z, v.w));
#pragma unroll
        for (int off = 8; off > 0; off >>= 1) {
            lmn = fminf(lmn, __shfl_down_sync(0xffffffffu, lmn, off, 16));
            lmx = fmaxf(lmx, __shfl_down_sync(0xffffffffu, lmx, off, 16));
        }
        if (tx == 0) {
            atomicMinF(&g_h3_min[s * C_ + o], lmn);
            atomicMaxF(&g_h3_max[s * C_ + o], lmx);
        }
    }
}

// In-place final range_bn + relu on d_out.
__global__ __launch_bounds__(256) void final_kernel(float4* __restrict__ out) {
    const float mn3 = g_mn[3], s3 = g_sc[3];
    size_t stride = (size_t)gridDim.x * blockDim.x;
    for (size_t i = (size_t)blockIdx.x * blockDim.x + threadIdx.x; i < TOT_ / 4; i += stride) {
        int plane = (int)(i / (HW_ / 4));   // s*256 + o  (3136 % 4 == 0)
        int o = plane & 255;
        float A = g_A2[o], Cv = g_C2[o];
        float4 v = out[i];
        v.x = fmaxf(A * quantf(v.x, mn3, s3) + Cv, 0.f);
        v.y = fmaxf(A * quantf(v.y, mn3, s3) + Cv, 0.f);
        v.z = fmaxf(A * quantf(v.z, mn3, s3) + Cv, 0.f);
        v.w = fmaxf(A * quantf(v.w, mn3, s3) + Cv, 0.f);
        out[i] = v;
    }
}

extern "C" void kernel_launch(void* const* d_in, const int* in_sizes, int n_in,
                              void* d_out, int out_size) {
    const float* x     = (const float*)d_in[0];
    const float* dw_w  = (const float*)d_in[1];
    const float* dw_b  = (const float*)d_in[2];
    const float* bn1_w = (const float*)d_in[3];
    const float* bn1_b = (const float*)d_in[4];
    const float* pw_w  = (const float*)d_in[5];
    const float* bn2_w = (const float*)d_in[6];
    const float* bn2_b = (const float*)d_in[7];
    float* out = (float*)d_out;

    init_kernel<<<32, 256>>>();
    xminmax_kernel<<<dim3(98, B_), 256>>>(x);
    pwminmax_kernel<<<64, 256>>>(pw_w);
    prep1_kernel<<<1, 256>>>(dw_w, dw_b, bn1_w, bn2_w);
    quantpw_kernel<<<256, 256>>>(pw_w);
    conv_kernel<<<dim3(C_, B_), 256>>>(x);
    prep_stats_kernel<<<1, 256>>>(0);
    qsum_kernel<<<dim3(C_, B_), 256>>>(nullptr, 0);
    prep_mean_kernel<<<1, 256>>>(0, bn1_b);
    gemm_kernel<<<dim3(HW_ / BN, C_ / BM, B_), 256>>>(out);
    prep_stats_kernel<<<1, 256>>>(1);
    qsum_kernel<<<dim3(C_, B_), 256>>>(out, 1);
    prep_mean_kernel<<<1, 256>>>(1, bn2_b);
    final_kernel<<<4096, 256>>>((float4*)out);
}

// round 3
// speedup vs baseline: 1.8584x; 1.8584x over previous
#include <cuda_runtime.h>
#include <cuda_bf16.h>
#include <math.h>
#include <stdint.h>

// Problem constants
#define B_    32
#define C_    256
#define H_    56
#define W_    56
#define HW_   3136
#define CHW_  802816      // 256*3136
#define TOT_  25690112    // 32*256*3136
#define NCH_  16          // chunks
#define QMAX_ 255.0f

#define FINF __int_as_float(0x7f800000)

// ---------------- device globals (scratch; no allocations allowed) ----------------
__device__ float h1_buf[TOT_];                  // depthwise conv output (103 MB)
__device__ unsigned char i_buf[TOT_];           // u8 quant indices (26 MB), reused stage0/stage1
__device__ unsigned int  b_pk[B_ * 64 * HW_];   // packed B operand [s][k=c/4][p] (26 MB)

__device__ float g_x_smin[B_], g_x_smax[B_];
__device__ float g_h1_min[B_ * C_], g_h1_max[B_ * C_];   // per (s,c)
__device__ float g_h3_min[B_ * C_], g_h3_max[B_ * C_];   // per (s,o)
__device__ int   g_isum1[C_], g_isum2[C_];
__device__ float g_pw_mn, g_pw_mx, g_pw_sc;

__device__ float g_mn[4], g_sc[4];        // 0:x 1:h1 2:h2 3:h3 quantizer params
__device__ float g_qdw[C_ * 9], g_qdwb[C_], g_qbn1w[C_], g_qbn2w[C_];
__device__ unsigned int g_apk[64 * C_];   // packed weight indices [k=c/4][o]
__device__ float g_suma[C_];              // sum over c of a-index per o
__device__ float g_sumb[B_ * HW_];        // sum over c of b-index per (s,p)
__device__ unsigned char g_lut[C_ * 256]; // per-channel i->b LUT
__device__ float g_A1[C_], g_C1[C_], g_A2[C_], g_C2[C_];

// ---------------- helpers ----------------
__device__ __forceinline__ float quantf(float v, float mn, float sc) {
    float t = (v - mn) / sc;
    t = fminf(fmaxf(t, 0.f), QMAX_);
    return rintf(t) * sc + mn;
}

__device__ __forceinline__ void atomicMaxF(float* a, float v) {
    if (v >= 0.f) atomicMax((int*)a, __float_as_int(v));
    else          atomicMin((unsigned int*)a, __float_as_uint(v));
}
__device__ __forceinline__ void atomicMinF(float* a, float v) {
    if (v >= 0.f) atomicMin((int*)a, __float_as_int(v));
    else          atomicMax((unsigned int*)a, __float_as_uint(v));
}

// blockDim.x == 256 assumed. sh must hold 512 floats.
__device__ float2 blockMinMax256(float lmn, float lmx, float* sh) {
    int t = threadIdx.x;
    __syncthreads();
    sh[t] = lmn; sh[256 + t] = lmx;
    __syncthreads();
    for (int o = 128; o > 0; o >>= 1) {
        if (t < o) {
            sh[t]       = fminf(sh[t], sh[t + o]);
            sh[256 + t] = fmaxf(sh[256 + t], sh[256 + t + o]);
        }
        __syncthreads();
    }
    float2 r = make_float2(sh[0], sh[256]);
    __syncthreads();
    return r;
}

// ---------------- kernels ----------------
__global__ void init_kernel() {
    int i = blockIdx.x * blockDim.x + threadIdx.x;
    if (i < B_ * C_) {
        g_h1_min[i] = FINF; g_h1_max[i] = -FINF;
        g_h3_min[i] = FINF; g_h3_max[i] = -FINF;
    }
    if (i < C_) { g_isum1[i] = 0; g_isum2[i] = 0; }
    if (i < B_) { g_x_smin[i] = FINF; g_x_smax[i] = -FINF; }
    if (i == 0) { g_pw_mn = FINF; g_pw_mx = -FINF; }
}

__global__ __launch_bounds__(256) void xminmax_kernel(const float* __restrict__ x) {
    __shared__ float sh[512];
    int s = blockIdx.y;
    const float* xp = x + (size_t)s * CHW_;
    float mn = FINF, mx = -FINF;
    for (int i = blockIdx.x * blockDim.x + threadIdx.x; i < CHW_; i += gridDim.x * blockDim.x) {
        float v = xp[i];
        mn = fminf(mn, v); mx = fmaxf(mx, v);
    }
    float2 r = blockMinMax256(mn, mx, sh);
    if (threadIdx.x == 0) { atomicMinF(&g_x_smin[s], r.x); atomicMaxF(&g_x_smax[s], r.y); }
}

__global__ __launch_bounds__(256) void pwminmax_kernel(const float* __restrict__ pw) {
    __shared__ float sh[512];
    float mn = FINF, mx = -FINF;
    for (int i = blockIdx.x * blockDim.x + threadIdx.x; i < C_ * C_; i += gridDim.x * blockDim.x) {
        float v = pw[i];
        mn = fminf(mn, v); mx = fmaxf(mx, v);
    }
    float2 r = blockMinMax256(mn, mx, sh);
    if (threadIdx.x == 0) { atomicMinF(&g_pw_mn, r.x); atomicMaxF(&g_pw_mx, r.y); }
}

__global__ __launch_bounds__(256) void prep1_kernel(const float* __restrict__ dw_w,
                                                    const float* __restrict__ dw_b,
                                                    const float* __restrict__ bn1_w,
                                                    const float* __restrict__ bn2_w) {
    __shared__ float sh[512];
    int t = threadIdx.x;
    if (t == 0) {
        float a = 0.f, b = 0.f;
        for (int s = 0; s < B_; s++) { a += g_x_smin[s]; b += g_x_smax[s]; }
        float mn = a / 32.f, mx = b / 32.f;
        g_mn[0] = mn;
        g_sc[0] = fmaxf((mx - mn) / QMAX_, 1e-8f);
    }
    // depthwise weights (2304)
    {
        float mn = FINF, mx = -FINF;
        for (int i = t; i < C_ * 9; i += 256) { float v = dw_w[i]; mn = fminf(mn, v); mx = fmaxf(mx, v); }
        float2 r = blockMinMax256(mn, mx, sh);
        float sc = fmaxf((r.y - r.x) / QMAX_, 1e-8f);
        for (int i = t; i < C_ * 9; i += 256) g_qdw[i] = quantf(dw_w[i], r.x, sc);
    }
    // depthwise bias (256)
    {
        float v = dw_b[t];
        float2 r = blockMinMax256(v, v, sh);
        float sc = fmaxf((r.y - r.x) / QMAX_, 1e-8f);
        g_qdwb[t] = quantf(v, r.x, sc);
    }
    // bn1_w (256)
    {
        float v = bn1_w[t];
        float2 r = blockMinMax256(v, v, sh);
        float sc = fmaxf((r.y - r.x) / QMAX_, 1e-8f);
        g_qbn1w[t] = quantf(v, r.x, sc);
    }
    // bn2_w (256)
    {
        float v = bn2_w[t];
        float2 r = blockMinMax256(v, v, sh);
        float sc = fmaxf((r.y - r.x) / QMAX_, 1e-8f);
        g_qbn2w[t] = quantf(v, r.x, sc);
    }
}

// Pack pointwise weight indices: a = rint(clip((w - wmn)/sw)), layout [k=c/4][o], + suma per o.
__global__ __launch_bounds__(256) void packpw_kernel(const float* __restrict__ pw) {
    int o = threadIdx.x;
    float mn = g_pw_mn, mx = g_pw_mx;
    float sc = fmaxf((mx - mn) / QMAX_, 1e-8f);
    if (o == 0) g_pw_sc = sc;
    unsigned int suma = 0;
#pragma unroll 4
    for (int k = 0; k < 64; k++) {
        float4 w = *reinterpret_cast<const float4*>(&pw[o * C_ + 4 * k]);
        float ws[4] = {w.x, w.y, w.z, w.w};
        unsigned int pk = 0;
#pragma unroll
        for (int j = 0; j < 4; j++) {
            float u = (ws[j] - mn) / sc;
            u = fminf(fmaxf(u, 0.f), QMAX_);
            pk |= ((unsigned int)(int)rintf(u)) << (8 * j);
        }
        g_apk[k * C_ + o] = pk;
        suma = __dp4a(pk, 0x01010101u, suma);
    }
    g_suma[o] = (float)suma;
}

// Depthwise 3x3, pad 1. One block per (s,c) plane. Fused input quantization,
// quantized weights/bias, per-(s,c) min/max of output (exact, no atomics).
__global__ __launch_bounds__(256) void conv_kernel(const float* __restrict__ x) {
    int c = blockIdx.x, s = blockIdx.y;
    __shared__ float tile[58 * 58];
    __shared__ float sh[512];
    const float mn0 = g_mn[0], s0 = g_sc[0];
    const float* xp = x + ((size_t)s * C_ + c) * HW_;
    int t = threadIdx.x;
    for (int i = t; i < 58 * 58; i += 256) {
        int r = i / 58, q = i - r * 58;
        int gy = r - 1, gx = q - 1;
        float v = 0.f;  // zero padding is NOT quantized
        if ((unsigned)gy < 56u && (unsigned)gx < 56u) v = quantf(xp[gy * 56 + gx], mn0, s0);
        tile[i] = v;
    }
    float w[9];
#pragma unroll
    for (int k = 0; k < 9; k++) w[k] = g_qdw[c * 9 + k];
    float bias = g_qdwb[c];
    __syncthreads();
    float* hp = h1_buf + ((size_t)s * C_ + c) * HW_;
    float mn = FINF, mx = -FINF;
    for (int p = t; p < HW_; p += 256) {
        int yy = p / 56, xx = p - yy * 56;
        const float* tp = tile + yy * 58 + xx;
        float acc = bias;
        acc += tp[0] * w[0] + tp[1] * w[1] + tp[2] * w[2];
        acc += tp[58] * w[3] + tp[59] * w[4] + tp[60] * w[5];
        acc += tp[116] * w[6] + tp[117] * w[7] + tp[118] * w[8];
        hp[p] = acc;
        mn = fminf(mn, acc); mx = fmaxf(mx, acc);
    }
    float2 r = blockMinMax256(mn, mx, sh);
    if (t == 0) { g_h1_min[s * C_ + c] = r.x; g_h1_max[s * C_ + c] = r.y; }
}

// stage 0: h1 stats -> g_mn[1],g_sc[1], A1 ; stage 1: h3 stats -> g_mn[3],g_sc[3], A2
__global__ __launch_bounds__(256) void prep_stats_kernel(int stage) {
    int t = threadIdx.x;
    const float* MN  = stage ? g_h3_min : g_h1_min;
    const float* MX  = stage ? g_h3_max : g_h1_max;
    const float* QBW = stage ? g_qbn2w : g_qbn1w;
    float* A = stage ? g_A2 : g_A1;
    int qi = stage ? 3 : 1;

    __shared__ float smn[B_], smx[B_];
    __shared__ float s_mn, s_s;
    if (t < B_) {
        float mn = FINF, mx = -FINF;
        for (int c = 0; c < C_; c++) {
            mn = fminf(mn, MN[t * C_ + c]);
            mx = fmaxf(mx, MX[t * C_ + c]);
        }
        smn[t] = mn; smx[t] = mx;
    }
    __syncthreads();
    if (t == 0) {
        float a = 0.f, b = 0.f;
        for (int s = 0; s < B_; s++) { a += smn[s]; b += smx[s]; }
        float mn = a / 32.f, mx = b / 32.f;
        s_mn = mn;
        s_s = fmaxf((mx - mn) / QMAX_, 1e-8f);
        g_mn[qi] = s_mn; g_sc[qi] = s_s;
    }
    __syncthreads();
    float mn = s_mn, sv = s_s;

    // per-channel chunk stats; chunk j == samples {2j, 2j+1}; quantize is monotone
    float amax = 0.f, amin = 0.f;
    for (int j = 0; j < NCH_; j++) {
        float cmx = fmaxf(MX[(2 * j) * C_ + t], MX[(2 * j + 1) * C_ + t]);
        float cmn = fminf(MN[(2 * j) * C_ + t], MN[(2 * j + 1) * C_ + t]);
        amax += quantf(cmx, mn, sv);
        amin += quantf(cmn, mn, sv);
    }
    float mean_max = amax * (1.f / 16.f), mean_min = amin * (1.f / 16.f);
    double sfd = 0.175 * (1.0 + sqrt(3.141592653589793 * 1.3862943611198906))
               / sqrt(2.0 * log(6272.0));
    float sf = (float)sfd;
    float rs = 1.0f / ((mean_max - mean_min) * sf + 1e-5f);

    __shared__ float sh[512];
    float2 r = blockMinMax256(rs, rs, sh);
    float rsc = fmaxf((r.y - r.x) / QMAX_, 1e-8f);
    float qs = quantf(rs, r.x, rsc);
    A[t] = qs * QBW[t];
}

// Quantize pass: write u8 indices + exact integer per-channel sums.
// stage 0: src = h1_buf with q-params idx 1. stage 1: src = d_out with idx 3.
__global__ __launch_bounds__(256) void quantsum_kernel(const float* __restrict__ ext, int stage) {
    int c = blockIdx.x, s = blockIdx.y;
    float mn = g_mn[stage ? 3 : 1], sv = g_sc[stage ? 3 : 1];
    const float* hp = (stage ? ext : (const float*)h1_buf) + ((size_t)s * C_ + c) * HW_;
    unsigned char* op = i_buf + ((size_t)s * C_ + c) * HW_;
    int acc = 0;
    for (int p = threadIdx.x; p < HW_; p += 256) {
        float t = (hp[p] - mn) / sv;
        t = fminf(fmaxf(t, 0.f), QMAX_);
        int i = (int)rintf(t);
        op[p] = (unsigned char)i;
        acc += i;
    }
    __shared__ int sd[256];
    sd[threadIdx.x] = acc;
    __syncthreads();
    for (int o = 128; o > 0; o >>= 1) {
        if (threadIdx.x < o) sd[threadIdx.x] += sd[threadIdx.x + o];
        __syncthreads();
    }
    if (threadIdx.x == 0) atomicAdd(stage ? &g_isum2[c] : &g_isum1[c], sd[0]);
}

// stage 0: C1 from isum1 + derive h2 quantizer (mn2/s2) + build i->b LUT. stage 1: C2 from isum2.
__global__ __launch_bounds__(256) void prep_mean_kernel(int stage, const float* __restrict__ bias) {
    int t = threadIdx.x;
    const float* A = stage ? g_A2 : g_A1;
    float* Cc = stage ? g_C2 : g_C1;
    float mnq = g_mn[stage ? 3 : 1], sq = g_sc[stage ? 3 : 1];
    int isum = stage ? g_isum2[t] : g_isum1[t];
    float mean = mnq + sq * ((float)isum * (1.0f / 100352.0f));
    Cc[t] = bias[t] - mean * A[t];
    if (stage == 0) {
        __syncthreads();
        float mn1 = g_mn[1], s1 = g_sc[1];
        __shared__ float smn[B_], smx[B_];
        if (t < B_) {
            float lo = FINF, hi = -FINF;
            for (int c = 0; c < C_; c++) {
                float Aa = g_A1[c], Cv = g_C1[c];
                float v1 = Aa * quantf(g_h1_max[t * C_ + c], mn1, s1) + Cv;
                float v2 = Aa * quantf(g_h1_min[t * C_ + c], mn1, s1) + Cv;
                hi = fmaxf(hi, fmaxf(fmaxf(v1, v2), 0.f));
                lo = fminf(lo, fmaxf(fminf(v1, v2), 0.f));
            }
            smn[t] = lo; smx[t] = hi;
        }
        __syncthreads();
        if (t == 0) {
            float a = 0.f, b = 0.f;
            for (int s = 0; s < B_; s++) { a += smn[s]; b += smx[s]; }
            float mn2 = a / 32.f, mx2 = b / 32.f;
            g_mn[2] = mn2;
            g_sc[2] = fmaxf((mx2 - mn2) / QMAX_, 1e-8f);
        }
        __syncthreads();
        // Build per-channel LUT: i -> b index of quantized h2
        float mn2 = g_mn[2], s2v = g_sc[2];
        float Aa = g_A1[t], Cv = g_C1[t];
        for (int i = 0; i < 256; i++) {
            float q1 = mn1 + (float)i * s1;
            float h2 = fmaxf(Aa * q1 + Cv, 0.f);
            float u = (h2 - mn2) / s2v;
            u = fminf(fmaxf(u, 0.f), QMAX_);
            g_lut[t * 256 + i] = (unsigned char)(int)rintf(u);
        }
    }
}

// Remap i_buf -> packed B operand [s][k][p] u32 via LUT, plus per-pixel sum of b.
__global__ __launch_bounds__(256) void remap_kernel() {
    int s = blockIdx.y;
    int p = blockIdx.x * 256 + threadIdx.x;
    if (p >= HW_) return;
    const unsigned char* ip = i_buf + (size_t)s * CHW_;
    unsigned int* bp = b_pk + (size_t)s * 64 * HW_;
    unsigned int sum = 0;
#pragma unroll 4
    for (int k = 0; k < 64; k++) {
        unsigned int pk = 0;
#pragma unroll
        for (int j = 0; j < 4; j++) {
            int c = 4 * k + j;
            unsigned int ii = ip[(size_t)c * HW_ + p];
            pk |= (unsigned int)g_lut[c * 256 + ii] << (8 * j);
        }
        bp[k * HW_ + p] = pk;
        sum = __dp4a(pk, 0x01010101u, sum);
    }
    g_sumb[s * HW_ + p] = (float)sum;
}

// Exact integer pointwise GEMM via dp4a. Tile: 128 o x 64 p, K=256 (64 packs) fully in smem.
// Epilogue reconstructs fp32 output: sw*s2*dot + wmn*s2*sumb + mn2*sw*suma + 256*wmn*mn2,
// and tracks per-(s,o) min/max.
__global__ __launch_bounds__(256) void gemm_kernel(float* __restrict__ out) {
    int s = blockIdx.z;
    int om = blockIdx.y * 128;
    int pn = blockIdx.x * 64;
    __shared__ unsigned int As[64][128];   // [k][o]  32KB
    __shared__ unsigned int Bs[64][64];    // [k][p]  16KB
    int tid = threadIdx.x;
#pragma unroll
    for (int j = 0; j < 32; j++) {
        int e = tid + 256 * j;
        int k = e >> 7, m = e & 127;
        As[k][m] = g_apk[k * C_ + om + m];
    }
    const unsigned int* bp = b_pk + (size_t)s * 64 * HW_;
#pragma unroll
    for (int j = 0; j < 16; j++) {
        int e = tid + 256 * j;
        int k = e >> 6, p = e & 63;
        Bs[k][p] = bp[k * HW_ + pn + p];
    }
    __syncthreads();

    int tx = tid & 15, ty = tid >> 4;
    unsigned int acc[8][4];
#pragma unroll
    for (int i = 0; i < 8; i++)
#pragma unroll
        for (int j = 0; j < 4; j++) acc[i][j] = 0u;

#pragma unroll 8
    for (int k = 0; k < 64; k++) {
        uint4 a0 = *reinterpret_cast<const uint4*>(&As[k][ty * 8]);
        uint4 a1 = *reinterpret_cast<const uint4*>(&As[k][ty * 8 + 4]);
        uint4 bv = *reinterpret_cast<const uint4*>(&Bs[k][tx * 4]);
        unsigned int a[8] = {a0.x, a0.y, a0.z, a0.w, a1.x, a1.y, a1.z, a1.w};
        unsigned int b[4] = {bv.x, bv.y, bv.z, bv.w};
#pragma unroll
        for (int i = 0; i < 8; i++)
#pragma unroll
            for (int j = 0; j < 4; j++)
                acc[i][j] = __dp4a(a[i], b[j], acc[i][j]);
    }

    float wmn = g_pw_mn, sw = g_pw_sc;
    float mn2 = g_mn[2], s2 = g_sc[2];
    float c0 = sw * s2;
    float cb = wmn * s2;
    float ca = mn2 * sw;
    float kconst = 256.f * wmn * mn2;
    float sb[4];
#pragma unroll
    for (int j = 0; j < 4; j++) sb[j] = g_sumb[s * HW_ + pn + tx * 4 + j];

#pragma unroll
    for (int i = 0; i < 8; i++) {
        int o = om + ty * 8 + i;
        float base = ca * g_suma[o] + kconst;
        float r0 = c0 * (float)acc[i][0] + cb * sb[0] + base;
        float r1 = c0 * (float)acc[i][1] + cb * sb[1] + base;
        float r2 = c0 * (float)acc[i][2] + cb * sb[2] + base;
        float r3 = c0 * (float)acc[i][3] + cb * sb[3] + base;
        float4 v = make_float4(r0, r1, r2, r3);
        *reinterpret_cast<float4*>(&out[((size_t)s * C_ + o) * HW_ + pn + tx * 4]) = v;
        float lmn = fminf(fminf(r0, r1), fminf(r2, r3));
        float lmx = fmaxf(fmaxf(r0, r1), fmaxf(r2, r3));
#pragma unroll
        for (int off = 8; off > 0; off >>= 1) {
            lmn = fminf(lmn, __shfl_down_sync(0xffffffffu, lmn, off, 16));
            lmx = fmaxf(lmx, __shfl_down_sync(0xffffffffu, lmx, off, 16));
        }
        if (tx == 0) {
            atomicMinF(&g_h3_min[s * C_ + o], lmn);
            atomicMaxF(&g_h3_max[s * C_ + o], lmx);
        }
    }
}

// In-place final range_bn + relu: read u8 indices, write fp32 out.
__global__ __launch_bounds__(256) void final_kernel(float4* __restrict__ out) {
    const float mn3 = g_mn[3], s3 = g_sc[3];
    const uchar4* ib = reinterpret_cast<const uchar4*>(i_buf);
    size_t stride = (size_t)gridDim.x * blockDim.x;
    for (size_t i = (size_t)blockIdx.x * blockDim.x + threadIdx.x; i < TOT_ / 4; i += stride) {
        int plane = (int)(i / (HW_ / 4));   // s*256 + o  (3136 % 4 == 0)
        int o = plane & 255;
        float A = g_A2[o], Cv = g_C2[o];
        uchar4 q = ib[i];
        float4 v;
        v.x = fmaxf(A * (mn3 + (float)q.x * s3) + Cv, 0.f);
        v.y = fmaxf(A * (mn3 + (float)q.y * s3) + Cv, 0.f);
        v.z = fmaxf(A * (mn3 + (float)q.z * s3) + Cv, 0.f);
        v.w = fmaxf(A * (mn3 + (float)q.w * s3) + Cv, 0.f);
        out[i] = v;
    }
}

extern "C" void kernel_launch(void* const* d_in, const int* in_sizes, int n_in,
                              void* d_out, int out_size) {
    const float* x     = (const float*)d_in[0];
    const float* dw_w  = (const float*)d_in[1];
    const float* dw_b  = (const float*)d_in[2];
    const float* bn1_w = (const float*)d_in[3];
    const float* bn1_b = (const float*)d_in[4];
    const float* pw_w  = (const float*)d_in[5];
    const float* bn2_w = (const float*)d_in[6];
    const float* bn2_b = (const float*)d_in[7];
    float* out = (float*)d_out;

    init_kernel<<<32, 256>>>();
    xminmax_kernel<<<dim3(98, B_), 256>>>(x);
    pwminmax_kernel<<<64, 256>>>(pw_w);
    prep1_kernel<<<1, 256>>>(dw_w, dw_b, bn1_w, bn2_w);
    packpw_kernel<<<1, 256>>>(pw_w);
    conv_kernel<<<dim3(C_, B_), 256>>>(x);
    prep_stats_kernel<<<1, 256>>>(0);
    quantsum_kernel<<<dim3(C_, B_), 256>>>(nullptr, 0);
    prep_mean_kernel<<<1, 256>>>(0, bn1_b);
    remap_kernel<<<dim3(13, B_), 256>>>();
    gemm_kernel<<<dim3(HW_ / 64, 2, B_), 256>>>(out);
    prep_stats_kernel<<<1, 256>>>(1);
    quantsum_kernel<<<dim3(C_, B_), 256>>>(out, 1);
    prep_mean_kernel<<<1, 256>>>(1, bn2_b);
    final_kernel<<<4096, 256>>>((float4*)out);
}

// round 4
// speedup vs baseline: 2.4985x; 1.3445x over previous
#include <cuda_runtime.h>
#include <cuda_bf16.h>
#include <math.h>
#include <stdint.h>

// Problem constants
#define B_    32
#define C_    256
#define H_    56
#define W_    56
#define HW_   3136
#define CHW_  802816      // 256*3136
#define TOT_  25690112    // 32*256*3136
#define NCH_  16          // chunks
#define QMAX_ 255.0f

#define FINF __int_as_float(0x7f800000)

// ---------------- device globals (scratch; no allocations allowed) ----------------
__device__ float h1_buf[TOT_];                  // depthwise conv output (103 MB)
__device__ unsigned char i_buf[TOT_];           // u8 quant indices (26 MB), reused stage0/stage1
__device__ unsigned int  b_pk[B_ * 64 * HW_];   // packed B operand [s][k=c/4][p] (26 MB)

__device__ float g_x_smin[B_], g_x_smax[B_];
__device__ float g_h1_min[B_ * C_], g_h1_max[B_ * C_];   // per (s,c)
__device__ float g_h3_min[B_ * C_], g_h3_max[B_ * C_];   // per (s,o)
__device__ int   g_isum1[C_], g_isum2[C_];
__device__ float g_pw_pmn[32], g_pw_pmx[32];    // per-block partials (no atomics)
__device__ float g_pw_mn, g_pw_sc;

__device__ float g_mn[4], g_sc[4], g_inv[4];    // 0:x 1:h1 2:h2 3:h3 quantizer params
__device__ float g_qdw[C_ * 9], g_qdwb[C_], g_qbn1w[C_], g_qbn2w[C_];
__device__ unsigned int g_apk[64 * C_];   // packed weight indices [k=c/4][o]
__device__ float g_suma[C_];              // sum over c of a-index per o
__device__ float g_sumb[B_ * HW_];        // sum over c of b-index per (s,p)
__device__ unsigned char g_lut[C_ * 256]; // per-channel i->b LUT
__device__ float g_A1[C_], g_C1[C_], g_A2[C_], g_C2[C_];

// ---------------- helpers ----------------
__device__ __forceinline__ float quantf(float v, float mn, float sc) {
    float t = (v - mn) / sc;
    t = fminf(fmaxf(t, 0.f), QMAX_);
    return rintf(t) * sc + mn;
}

__device__ __forceinline__ void atomicMaxF(float* a, float v) {
    if (v >= 0.f) atomicMax((int*)a, __float_as_int(v));
    else          atomicMin((unsigned int*)a, __float_as_uint(v));
}
__device__ __forceinline__ void atomicMinF(float* a, float v) {
    if (v >= 0.f) atomicMin((int*)a, __float_as_int(v));
    else          atomicMax((unsigned int*)a, __float_as_uint(v));
}

// 256-thread block min/max via warp shuffles. sh must hold 16 floats. 2 syncs.
__device__ float2 bmm256(float mn, float mx, float* sh) {
    int t = threadIdx.x, lane = t & 31, wid = t >> 5;
#pragma unroll
    for (int o = 16; o > 0; o >>= 1) {
        mn = fminf(mn, __shfl_xor_sync(0xffffffffu, mn, o));
        mx = fmaxf(mx, __shfl_xor_sync(0xffffffffu, mx, o));
    }
    __syncthreads();
    if (lane == 0) { sh[wid] = mn; sh[8 + wid] = mx; }
    __syncthreads();
    float rmn = FINF, rmx = -FINF;
#pragma unroll
    for (int i = 0; i < 8; i++) { rmn = fminf(rmn, sh[i]); rmx = fmaxf(rmx, sh[8 + i]); }
    return make_float2(rmn, rmx);
}

// ---------------- kernels ----------------
// blocks 0..31: init scratch; blocks 32..63: pointwise weight min/max partials
__global__ __launch_bounds__(256) void init_pw_kernel(const float* __restrict__ pw) {
    int b = blockIdx.x;
    if (b < 32) {
        int i = b * 256 + threadIdx.x;
        g_h3_min[i] = FINF; g_h3_max[i] = -FINF;
        if (i < C_) { g_isum1[i] = 0; g_isum2[i] = 0; }
        if (i < B_) { g_x_smin[i] = FINF; g_x_smax[i] = -FINF; }
    } else {
        int pb = b - 32;
        const float4* p4 = reinterpret_cast<const float4*>(pw);
        float mn = FINF, mx = -FINF;
        // 65536 floats = 16384 float4; 32 blocks x 256 threads x 2
        for (int i = pb * 512 + threadIdx.x; i < (pb + 1) * 512; i += 256) {
            float4 v = p4[i];
            mn = fminf(fminf(mn, fminf(v.x, v.y)), fminf(v.z, v.w));
            mx = fmaxf(fmaxf(mx, fmaxf(v.x, v.y)), fmaxf(v.z, v.w));
        }
        __shared__ float sh[16];
        float2 r = bmm256(mn, mx, sh);
        if (threadIdx.x == 0) { g_pw_pmn[pb] = r.x; g_pw_pmx[pb] = r.y; }
    }
}

__global__ __launch_bounds__(256) void xminmax_kernel(const float* __restrict__ x) {
    __shared__ float sh[16];
    int s = blockIdx.y;
    const float4* xp = reinterpret_cast<const float4*>(x + (size_t)s * CHW_);
    float mn = FINF, mx = -FINF;
    for (int i = blockIdx.x * 256 + threadIdx.x; i < CHW_ / 4; i += gridDim.x * 256) {
        float4 v = xp[i];
        mn = fminf(fminf(mn, fminf(v.x, v.y)), fminf(v.z, v.w));
        mx = fmaxf(fmaxf(mx, fmaxf(v.x, v.y)), fmaxf(v.z, v.w));
    }
    float2 r = bmm256(mn, mx, sh);
    if (threadIdx.x == 0) { atomicMinF(&g_x_smin[s], r.x); atomicMaxF(&g_x_smax[s], r.y); }
}

// Merged: x quantizer params, quantize dw/bias/bn weights, pw weight pack + suma.
__global__ __launch_bounds__(256) void prep1_kernel(const float* __restrict__ dw_w,
                                                    const float* __restrict__ dw_b,
                                                    const float* __restrict__ bn1_w,
                                                    const float* __restrict__ bn2_w,
                                                    const float* __restrict__ pw) {
    __shared__ float sh[16];
    __shared__ float s_wmn, s_wsc;
    int t = threadIdx.x;
    if (t == 0) {
        float a = 0.f, b = 0.f;
        for (int s = 0; s < B_; s++) { a += g_x_smin[s]; b += g_x_smax[s]; }
        float mn = a / 32.f, mx = b / 32.f;
        g_mn[0] = mn;
        float sc = fmaxf((mx - mn) / QMAX_, 1e-8f);
        g_sc[0] = sc; g_inv[0] = 1.f / sc;
    } else if (t == 32) {
        float mn = FINF, mx = -FINF;
        for (int i = 0; i < 32; i++) { mn = fminf(mn, g_pw_pmn[i]); mx = fmaxf(mx, g_pw_pmx[i]); }
        float sc = fmaxf((mx - mn) / QMAX_, 1e-8f);
        g_pw_mn = mn; g_pw_sc = sc;
        s_wmn = mn; s_wsc = sc;
    }
    // depthwise weights: thread t owns channel t's 9 taps
    float w9[9];
    float mn = FINF, mx = -FINF;
#pragma unroll
    for (int k = 0; k < 9; k++) {
        w9[k] = dw_w[t * 9 + k];
        mn = fminf(mn, w9[k]); mx = fmaxf(mx, w9[k]);
    }
    float2 r = bmm256(mn, mx, sh);
    {
        float sc = fmaxf((r.y - r.x) / QMAX_, 1e-8f);
#pragma unroll
        for (int k = 0; k < 9; k++) g_qdw[t * 9 + k] = quantf(w9[k], r.x, sc);
    }
    // depthwise bias
    {
        float v = dw_b[t];
        float2 rb = bmm256(v, v, sh);
        float sc = fmaxf((rb.y - rb.x) / QMAX_, 1e-8f);
        g_qdwb[t] = quantf(v, rb.x, sc);
    }
    // bn1_w
    {
        float v = bn1_w[t];
        float2 rb = bmm256(v, v, sh);
        float sc = fmaxf((rb.y - rb.x) / QMAX_, 1e-8f);
        g_qbn1w[t] = quantf(v, rb.x, sc);
    }
    // bn2_w
    {
        float v = bn2_w[t];
        float2 rb = bmm256(v, v, sh);
        float sc = fmaxf((rb.y - rb.x) / QMAX_, 1e-8f);
        g_qbn2w[t] = quantf(v, rb.x, sc);
    }
    __syncthreads();
    // pack pointwise weight indices [k=c/4][o] + suma per o
    {
        int o = t;
        float wmn = s_wmn, wsc = s_wsc;
        float winv = 1.f / wsc;
        unsigned int suma = 0;
#pragma unroll 4
        for (int k = 0; k < 64; k++) {
            float4 w = *reinterpret_cast<const float4*>(&pw[o * C_ + 4 * k]);
            float ws[4] = {w.x, w.y, w.z, w.w};
            unsigned int pk = 0;
#pragma unroll
            for (int j = 0; j < 4; j++) {
                float u = (ws[j] - wmn) * winv;
                u = fminf(fmaxf(u, 0.f), QMAX_);
                pk |= ((unsigned int)(int)rintf(u)) << (8 * j);
            }
            g_apk[k * C_ + o] = pk;
            suma = __dp4a(pk, 0x01010101u, suma);
        }
        g_suma[o] = (float)suma;
    }
}

// Depthwise 3x3, pad 1. One block per (s,c) plane. Fused input quantization,
// quantized weights/bias, per-(s,c) min/max of output (direct store, no atomics).
__global__ __launch_bounds__(256) void conv_kernel(const float* __restrict__ x) {
    int c = blockIdx.x, s = blockIdx.y;
    __shared__ float tile[58 * 58];
    __shared__ float sh[16];
    const float mn0 = g_mn[0], s0 = g_sc[0], i0 = g_inv[0];
    const float* xp = x + ((size_t)s * C_ + c) * HW_;
    int t = threadIdx.x;
    for (int i = t; i < 58 * 58; i += 256) {
        int r = i / 58, q = i - r * 58;
        int gy = r - 1, gx = q - 1;
        float v = 0.f;  // zero padding is NOT quantized
        if ((unsigned)gy < 56u && (unsigned)gx < 56u) {
            float u = (xp[gy * 56 + gx] - mn0) * i0;
            u = fminf(fmaxf(u, 0.f), QMAX_);
            v = rintf(u) * s0 + mn0;
        }
        tile[i] = v;
    }
    float w[9];
#pragma unroll
    for (int k = 0; k < 9; k++) w[k] = g_qdw[c * 9 + k];
    float bias = g_qdwb[c];
    __syncthreads();
    float* hp = h1_buf + ((size_t)s * C_ + c) * HW_;
    float mn = FINF, mx = -FINF;
    for (int p = t; p < HW_; p += 256) {
        int yy = p / 56, xx = p - yy * 56;
        const float* tp = tile + yy * 58 + xx;
        float acc = bias;
        acc += tp[0] * w[0] + tp[1] * w[1] + tp[2] * w[2];
        acc += tp[58] * w[3] + tp[59] * w[4] + tp[60] * w[5];
        acc += tp[116] * w[6] + tp[117] * w[7] + tp[118] * w[8];
        hp[p] = acc;
        mn = fminf(mn, acc); mx = fmaxf(mx, acc);
    }
    float2 r = bmm256(mn, mx, sh);
    if (t == 0) { g_h1_min[s * C_ + c] = r.x; g_h1_max[s * C_ + c] = r.y; }
}

// stage 0: h1 stats -> g_mn[1],g_sc[1], A1 ; stage 1: h3 stats -> g_mn[3],g_sc[3], A2
__global__ __launch_bounds__(256) void prep_stats_kernel(int stage) {
    int t = threadIdx.x;
    const float* MN  = stage ? g_h3_min : g_h1_min;
    const float* MX  = stage ? g_h3_max : g_h1_max;
    const float* QBW = stage ? g_qbn2w : g_qbn1w;
    float* A = stage ? g_A2 : g_A1;
    int qi = stage ? 3 : 1;

    __shared__ float pmn[256], pmx[256];
    __shared__ float smn[B_], smx[B_];
    __shared__ float s_mn, s_s;
    // per-sample extremes: 8 threads per sample, 32 channels each
    {
        int s = t >> 3, j = t & 7;
        float mn = FINF, mx = -FINF;
        for (int c = j * 32; c < j * 32 + 32; c++) {
            mn = fminf(mn, MN[s * C_ + c]);
            mx = fmaxf(mx, MX[s * C_ + c]);
        }
        pmn[t] = mn; pmx[t] = mx;
    }
    __syncthreads();
    if (t < B_) {
        float mn = FINF, mx = -FINF;
#pragma unroll
        for (int j = 0; j < 8; j++) {
            mn = fminf(mn, pmn[t * 8 + j]);
            mx = fmaxf(mx, pmx[t * 8 + j]);
        }
        smn[t] = mn; smx[t] = mx;
    }
    __syncthreads();
    if (t == 0) {
        float a = 0.f, b = 0.f;
        for (int s = 0; s < B_; s++) { a += smn[s]; b += smx[s]; }
        float mn = a / 32.f, mx = b / 32.f;
        s_mn = mn;
        s_s = fmaxf((mx - mn) / QMAX_, 1e-8f);
        g_mn[qi] = s_mn; g_sc[qi] = s_s; g_inv[qi] = 1.f / s_s;
    }
    __syncthreads();
    float mn = s_mn, sv = s_s;

    // per-channel chunk stats; chunk j == samples {2j, 2j+1}; quantize is monotone
    float amax = 0.f, amin = 0.f;
    for (int j = 0; j < NCH_; j++) {
        float cmx = fmaxf(MX[(2 * j) * C_ + t], MX[(2 * j + 1) * C_ + t]);
        float cmn = fminf(MN[(2 * j) * C_ + t], MN[(2 * j + 1) * C_ + t]);
        amax += quantf(cmx, mn, sv);
        amin += quantf(cmn, mn, sv);
    }
    float mean_max = amax * (1.f / 16.f), mean_min = amin * (1.f / 16.f);
    double sfd = 0.175 * (1.0 + sqrt(3.141592653589793 * 1.3862943611198906))
               / sqrt(2.0 * log(6272.0));
    float sf = (float)sfd;
    float rs = 1.0f / ((mean_max - mean_min) * sf + 1e-5f);

    __shared__ float sh[16];
    float2 r = bmm256(rs, rs, sh);
    float rsc = fmaxf((r.y - r.x) / QMAX_, 1e-8f);
    float qs = quantf(rs, r.x, rsc);
    A[t] = qs * QBW[t];
}

// Quantize pass: write u8 indices + exact integer per-channel sums. Vectorized.
// stage 0: src = h1_buf with q-params idx 1. stage 1: src = d_out with idx 3.
__global__ __launch_bounds__(256) void quantsum_kernel(const float* __restrict__ ext, int stage) {
    int c = blockIdx.x, s = blockIdx.y;
    int qi = stage ? 3 : 1;
    float mn = g_mn[qi], iv = g_inv[qi];
    const float4* hp = reinterpret_cast<const float4*>(
        (stage ? ext : (const float*)h1_buf) + ((size_t)s * C_ + c) * HW_);
    uchar4* op = reinterpret_cast<uchar4*>(i_buf + ((size_t)s * C_ + c) * HW_);
    int acc = 0;
    for (int p = threadIdx.x; p < HW_ / 4; p += 256) {
        float4 v = hp[p];
        float tx = fminf(fmaxf((v.x - mn) * iv, 0.f), QMAX_);
        float ty = fminf(fmaxf((v.y - mn) * iv, 0.f), QMAX_);
        float tz = fminf(fmaxf((v.z - mn) * iv, 0.f), QMAX_);
        float tw = fminf(fmaxf((v.w - mn) * iv, 0.f), QMAX_);
        int ix = (int)rintf(tx), iy = (int)rintf(ty), iz = (int)rintf(tz), iw = (int)rintf(tw);
        acc += ix + iy + iz + iw;
        op[p] = make_uchar4((unsigned char)ix, (unsigned char)iy, (unsigned char)iz, (unsigned char)iw);
    }
#pragma unroll
    for (int o = 16; o > 0; o >>= 1) acc += __shfl_xor_sync(0xffffffffu, acc, o);
    __shared__ int sd[8];
    int lane = threadIdx.x & 31, wid = threadIdx.x >> 5;
    if (lane == 0) sd[wid] = acc;
    __syncthreads();
    if (threadIdx.x == 0) {
        int tot = 0;
#pragma unroll
        for (int i = 0; i < 8; i++) tot += sd[i];
        atomicAdd(stage ? &g_isum2[c] : &g_isum1[c], tot);
    }
}

// stage 0: C1 from isum1 + derive h2 quantizer (mn2/s2) + build i->b LUT. stage 1: C2 from isum2.
__global__ __launch_bounds__(256) void prep_mean_kernel(int stage, const float* __restrict__ bias) {
    int t = threadIdx.x;
    const float* A = stage ? g_A2 : g_A1;
    float* Cc = stage ? g_C2 : g_C1;
    float mnq = g_mn[stage ? 3 : 1], sq = g_sc[stage ? 3 : 1];
    int isum = stage ? g_isum2[t] : g_isum1[t];
    float mean = mnq + sq * ((float)isum * (1.0f / 100352.0f));
    Cc[t] = bias[t] - mean * A[t];
    if (stage == 0) {
        __syncthreads();
        float mn1 = g_mn[1], s1 = g_sc[1];
        __shared__ float pmn[256], pmx[256];
        __shared__ float smn[B_], smx[B_];
        // 8 threads per sample, 32 channels each
        {
            int s = t >> 3, j = t & 7;
            float lo = FINF, hi = -FINF;
            for (int c = j * 32; c < j * 32 + 32; c++) {
                float Aa = g_A1[c], Cv = g_C1[c];
                float v1 = Aa * quantf(g_h1_max[s * C_ + c], mn1, s1) + Cv;
                float v2 = Aa * quantf(g_h1_min[s * C_ + c], mn1, s1) + Cv;
                hi = fmaxf(hi, fmaxf(fmaxf(v1, v2), 0.f));
                lo = fminf(lo, fmaxf(fminf(v1, v2), 0.f));
            }
            pmn[t] = lo; pmx[t] = hi;
        }
        __syncthreads();
        if (t < B_) {
            float lo = FINF, hi = -FINF;
#pragma unroll
            for (int j = 0; j < 8; j++) {
                lo = fminf(lo, pmn[t * 8 + j]);
                hi = fmaxf(hi, pmx[t * 8 + j]);
            }
            smn[t] = lo; smx[t] = hi;
        }
        __syncthreads();
        if (t == 0) {
            float a = 0.f, b = 0.f;
            for (int s = 0; s < B_; s++) { a += smn[s]; b += smx[s]; }
            float mn2 = a / 32.f, mx2 = b / 32.f;
            g_mn[2] = mn2;
            g_sc[2] = fmaxf((mx2 - mn2) / QMAX_, 1e-8f);
        }
        __syncthreads();
        // Build per-channel LUT: i -> b index of quantized h2
        float mn2 = g_mn[2], s2v = g_sc[2];
        float inv2 = 1.f / s2v;
        float Aa = g_A1[t], Cv = g_C1[t];
        for (int i = 0; i < 256; i++) {
            float q1 = mn1 + (float)i * s1;
            float h2 = fmaxf(Aa * q1 + Cv, 0.f);
            float u = (h2 - mn2) * inv2;
            u = fminf(fmaxf(u, 0.f), QMAX_);
            g_lut[t * 256 + i] = (unsigned char)(int)rintf(u);
        }
    }
}

// Remap i_buf -> packed B operand [s][k][p] u32 via LUT, plus per-pixel sum of b.
__global__ __launch_bounds__(256) void remap_kernel() {
    int s = blockIdx.y;
    int p = blockIdx.x * 256 + threadIdx.x;
    if (p >= HW_) return;
    const unsigned char* ip = i_buf + (size_t)s * CHW_;
    unsigned int* bp = b_pk + (size_t)s * 64 * HW_;
    unsigned int sum = 0;
#pragma unroll 4
    for (int k = 0; k < 64; k++) {
        unsigned int pk = 0;
#pragma unroll
        for (int j = 0; j < 4; j++) {
            int c = 4 * k + j;
            unsigned int ii = ip[(size_t)c * HW_ + p];
            pk |= (unsigned int)g_lut[c * 256 + ii] << (8 * j);
        }
        bp[k * HW_ + p] = pk;
        sum = __dp4a(pk, 0x01010101u, sum);
    }
    g_sumb[s * HW_ + p] = (float)sum;
}

// Exact integer pointwise GEMM via dp4a. Tile: 128 o x 64 p, K=256 (64 packs) fully in smem.
__global__ __launch_bounds__(256) void gemm_kernel(float* __restrict__ out) {
    int s = blockIdx.z;
    int om = blockIdx.y * 128;
    int pn = blockIdx.x * 64;
    __shared__ unsigned int As[64][128];   // [k][o]  32KB
    __shared__ unsigned int Bs[64][64];    // [k][p]  16KB
    int tid = threadIdx.x;
#pragma unroll
    for (int j = 0; j < 32; j++) {
        int e = tid + 256 * j;
        int k = e >> 7, m = e & 127;
        As[k][m] = g_apk[k * C_ + om + m];
    }
    const unsigned int* bp = b_pk + (size_t)s * 64 * HW_;
#pragma unroll
    for (int j = 0; j < 16; j++) {
        int e = tid + 256 * j;
        int k = e >> 6, p = e & 63;
        Bs[k][p] = bp[k * HW_ + pn + p];
    }
    __syncthreads();

    int tx = tid & 15, ty = tid >> 4;
    unsigned int acc[8][4];
#pragma unroll
    for (int i = 0; i < 8; i++)
#pragma unroll
        for (int j = 0; j < 4; j++) acc[i][j] = 0u;

#pragma unroll 8
    for (int k = 0; k < 64; k++) {
        uint4 a0 = *reinterpret_cast<const uint4*>(&As[k][ty * 8]);
        uint4 a1 = *reinterpret_cast<const uint4*>(&As[k][ty * 8 + 4]);
        uint4 bv = *reinterpret_cast<const uint4*>(&Bs[k][tx * 4]);
        unsigned int a[8] = {a0.x, a0.y, a0.z, a0.w, a1.x, a1.y, a1.z, a1.w};
        unsigned int b[4] = {bv.x, bv.y, bv.z, bv.w};
#pragma unroll
        for (int i = 0; i < 8; i++)
#pragma unroll
            for (int j = 0; j < 4; j++)
                acc[i][j] = __dp4a(a[i], b[j], acc[i][j]);
    }

    float wmn = g_pw_mn, sw = g_pw_sc;
    float mn2 = g_mn[2], s2 = g_sc[2];
    float c0 = sw * s2;
    float cb = wmn * s2;
    float ca = mn2 * sw;
    float kconst = 256.f * wmn * mn2;
    float sb[4];
#pragma unroll
    for (int j = 0; j < 4; j++) sb[j] = g_sumb[s * HW_ + pn + tx * 4 + j];

#pragma unroll
    for (int i = 0; i < 8; i++) {
        int o = om + ty * 8 + i;
        float base = ca * g_suma[o] + kconst;
        float r0 = c0 * (float)acc[i][0] + cb * sb[0] + base;
        float r1 = c0 * (float)acc[i][1] + cb * sb[1] + base;
        float r2 = c0 * (float)acc[i][2] + cb * sb[2] + base;
        float r3 = c0 * (float)acc[i][3] + cb * sb[3] + base;
        float4 v = make_float4(r0, r1, r2, r3);
        *reinterpret_cast<float4*>(&out[((size_t)s * C_ + o) * HW_ + pn + tx * 4]) = v;
        float lmn = fminf(fminf(r0, r1), fminf(r2, r3));
        float lmx = fmaxf(fmaxf(r0, r1), fmaxf(r2, r3));
#pragma unroll
        for (int off = 8; off > 0; off >>= 1) {
            lmn = fminf(lmn, __shfl_down_sync(0xffffffffu, lmn, off, 16));
            lmx = fmaxf(lmx, __shfl_down_sync(0xffffffffu, lmx, off, 16));
        }
        if (tx == 0) {
            atomicMinF(&g_h3_min[s * C_ + o], lmn);
            atomicMaxF(&g_h3_max[s * C_ + o], lmx);
        }
    }
}

// Final range_bn + relu: read u8 indices, write fp32 out.
__global__ __launch_bounds__(256) void final_kernel(float4* __restrict__ out) {
    const float mn3 = g_mn[3], s3 = g_sc[3];
    const uchar4* ib = reinterpret_cast<const uchar4*>(i_buf);
    size_t stride = (size_t)gridDim.x * blockDim.x;
    for (size_t i = (size_t)blockIdx.x * blockDim.x + threadIdx.x; i < TOT_ / 4; i += stride) {
        int plane = (int)(i / (HW_ / 4));   // s*256 + o  (3136 % 4 == 0)
        int o = plane & 255;
        float A = g_A2[o], Cv = g_C2[o];
        uchar4 q = ib[i];
        float4 v;
        v.x = fmaxf(A * (mn3 + (float)q.x * s3) + Cv, 0.f);
        v.y = fmaxf(A * (mn3 + (float)q.y * s3) + Cv, 0.f);
        v.z = fmaxf(A * (mn3 + (float)q.z * s3) + Cv, 0.f);
        v.w = fmaxf(A * (mn3 + (float)q.w * s3) + Cv, 0.f);
        out[i] = v;
    }
}

extern "C" void kernel_launch(void* const* d_in, const int* in_sizes, int n_in,
                              void* d_out, int out_size) {
    const float* x     = (const float*)d_in[0];
    const float* dw_w  = (const float*)d_in[1];
    const float* dw_b  = (const float*)d_in[2];
    const float* bn1_w = (const float*)d_in[3];
    const float* bn1_b = (const float*)d_in[4];
    const float* pw_w  = (const float*)d_in[5];
    const float* bn2_w = (const float*)d_in[6];
    const float* bn2_b = (const float*)d_in[7];
    float* out = (float*)d_out;

    init_pw_kernel<<<64, 256>>>(pw_w);                      // 0
    xminmax_kernel<<<dim3(49, B_), 256>>>(x);               // 1
    prep1_kernel<<<1, 256>>>(dw_w, dw_b, bn1_w, bn2_w, pw_w); // 2
    conv_kernel<<<dim3(C_, B_), 256>>>(x);                  // 3  <- ncu slot
    prep_stats_kernel<<<1, 256>>>(0);                       // 4
    quantsum_kernel<<<dim3(C_, B_), 256>>>(nullptr, 0);     // 5
    prep_mean_kernel<<<1, 256>>>(0, bn1_b);                 // 6
    remap_kernel<<<dim3(13, B_), 256>>>();                  // 7
    gemm_kernel<<<dim3(HW_ / 64, 2, B_), 256>>>(out);       // 8
    prep_stats_kernel<<<1, 256>>>(1);                       // 9
    quantsum_kernel<<<dim3(C_, B_), 256>>>(out, 1);         // 10
    prep_mean_kernel<<<1, 256>>>(1, bn2_b);                 // 11
    final_kernel<<<4096, 256>>>((float4*)out);              // 12
}

// round 5
// speedup vs baseline: 2.6694x; 1.0684x over previous
#include <cuda_runtime.h>
#include <cuda_bf16.h>
#include <math.h>
#include <stdint.h>

// Problem constants
#define B_    32
#define C_    256
#define H_    56
#define W_    56
#define HW_   3136
#define CHW_  802816      // 256*3136
#define TOT_  25690112    // 32*256*3136
#define NCH_  16          // chunks
#define QMAX_ 255.0f

#define FINF __int_as_float(0x7f800000)

// ---------------- device globals (scratch; no allocations allowed) ----------------
__device__ float h1_buf[TOT_];                  // depthwise conv output (103 MB)
__device__ unsigned char i_buf[TOT_];           // stage0: packed u32 [s][k][p]; stage1: u8 [s][c][p]

__device__ float g_x_smin[B_], g_x_smax[B_];
__device__ float g_h1_min[B_ * C_], g_h1_max[B_ * C_];   // per (s,c)
__device__ float g_h3_min[B_ * C_], g_h3_max[B_ * C_];   // per (s,o)
__device__ int   g_isum1[C_], g_isum2[C_];
__device__ float g_pw_pmn[32], g_pw_pmx[32];    // per-block partials (no atomics)
__device__ float g_pw_mn, g_pw_sc;

__device__ float g_mn[4], g_sc[4], g_inv[4];    // 0:x 1:h1 2:h2 3:h3 quantizer params
__device__ float g_qdw[C_ * 9], g_qdwb[C_], g_qbn1w[C_], g_qbn2w[C_];
__device__ unsigned int g_apk[64 * C_];   // packed weight indices [k=c/4][o]
__device__ float g_suma[C_];              // sum over c of a-index per o
__device__ unsigned char g_lut[C_ * 256]; // per-channel i->b LUT
__device__ float g_A1[C_], g_C1[C_], g_A2[C_], g_C2[C_];

// ---------------- helpers ----------------
__device__ __forceinline__ float quantf(float v, float mn, float sc) {
    float t = (v - mn) / sc;
    t = fminf(fmaxf(t, 0.f), QMAX_);
    return rintf(t) * sc + mn;
}

__device__ __forceinline__ void atomicMaxF(float* a, float v) {
    if (v >= 0.f) atomicMax((int*)a, __float_as_int(v));
    else          atomicMin((unsigned int*)a, __float_as_uint(v));
}
__device__ __forceinline__ void atomicMinF(float* a, float v) {
    if (v >= 0.f) atomicMin((int*)a, __float_as_int(v));
    else          atomicMax((unsigned int*)a, __float_as_uint(v));
}

// 256-thread block min/max via warp shuffles. sh must hold 16 floats. 2 syncs.
__device__ float2 bmm256(float mn, float mx, float* sh) {
    int t = threadIdx.x, lane = t & 31, wid = t >> 5;
#pragma unroll
    for (int o = 16; o > 0; o >>= 1) {
        mn = fminf(mn, __shfl_xor_sync(0xffffffffu, mn, o));
        mx = fmaxf(mx, __shfl_xor_sync(0xffffffffu, mx, o));
    }
    __syncthreads();
    if (lane == 0) { sh[wid] = mn; sh[8 + wid] = mx; }
    __syncthreads();
    float rmn = FINF, rmx = -FINF;
#pragma unroll
    for (int i = 0; i < 8; i++) { rmn = fminf(rmn, sh[i]); rmx = fmaxf(rmx, sh[8 + i]); }
    return make_float2(rmn, rmx);
}

// ---------------- kernels ----------------
// blocks 0..31: init scratch; 32..63: pw weight min/max partials; 64..1631: x per-sample min/max
__global__ __launch_bounds__(256) void init_x_kernel(const float* __restrict__ x,
                                                     const float* __restrict__ pw) {
    int b = blockIdx.x;
    if (b < 32) {
        int i = b * 256 + threadIdx.x;
        g_h3_min[i] = FINF; g_h3_max[i] = -FINF;
        if (i < C_) { g_isum1[i] = 0; g_isum2[i] = 0; }
        if (i < B_) { g_x_smin[i] = FINF; g_x_smax[i] = -FINF; }
    } else if (b < 64) {
        int pb = b - 32;
        const float4* p4 = reinterpret_cast<const float4*>(pw);
        float mn = FINF, mx = -FINF;
        for (int i = pb * 512 + threadIdx.x; i < (pb + 1) * 512; i += 256) {
            float4 v = p4[i];
            mn = fminf(fminf(mn, fminf(v.x, v.y)), fminf(v.z, v.w));
            mx = fmaxf(fmaxf(mx, fmaxf(v.x, v.y)), fmaxf(v.z, v.w));
        }
        __shared__ float sh[16];
        float2 r = bmm256(mn, mx, sh);
        if (threadIdx.x == 0) { g_pw_pmn[pb] = r.x; g_pw_pmx[pb] = r.y; }
    } else {
        int b2 = b - 64;
        int s = b2 / 49, blk = b2 % 49;
        const float4* xp = reinterpret_cast<const float4*>(x + (size_t)s * CHW_);
        float mn = FINF, mx = -FINF;
        for (int i = blk * 256 + threadIdx.x; i < CHW_ / 4; i += 49 * 256) {
            float4 v = xp[i];
            mn = fminf(fminf(mn, fminf(v.x, v.y)), fminf(v.z, v.w));
            mx = fmaxf(fmaxf(mx, fmaxf(v.x, v.y)), fmaxf(v.z, v.w));
        }
        __shared__ float sh[16];
        float2 r = bmm256(mn, mx, sh);
        if (threadIdx.x == 0) { atomicMinF(&g_x_smin[s], r.x); atomicMaxF(&g_x_smax[s], r.y); }
    }
}

// Merged: x quantizer params, quantize dw/bias/bn weights, pw weight pack + suma.
__global__ __launch_bounds__(256) void prep1_kernel(const float* __restrict__ dw_w,
                                                    const float* __restrict__ dw_b,
                                                    const float* __restrict__ bn1_w,
                                                    const float* __restrict__ bn2_w,
                                                    const float* __restrict__ pw) {
    __shared__ float sh[16];
    __shared__ float s_wmn, s_wsc;
    int t = threadIdx.x;
    if (t == 0) {
        float a = 0.f, b = 0.f;
        for (int s = 0; s < B_; s++) { a += g_x_smin[s]; b += g_x_smax[s]; }
        float mn = a / 32.f, mx = b / 32.f;
        g_mn[0] = mn;
        float sc = fmaxf((mx - mn) / QMAX_, 1e-8f);
        g_sc[0] = sc; g_inv[0] = 1.f / sc;
    } else if (t == 32) {
        float mn = FINF, mx = -FINF;
        for (int i = 0; i < 32; i++) { mn = fminf(mn, g_pw_pmn[i]); mx = fmaxf(mx, g_pw_pmx[i]); }
        float sc = fmaxf((mx - mn) / QMAX_, 1e-8f);
        g_pw_mn = mn; g_pw_sc = sc;
        s_wmn = mn; s_wsc = sc;
    }
    // depthwise weights: thread t owns channel t's 9 taps
    float w9[9];
    float mn = FINF, mx = -FINF;
#pragma unroll
    for (int k = 0; k < 9; k++) {
        w9[k] = dw_w[t * 9 + k];
        mn = fminf(mn, w9[k]); mx = fmaxf(mx, w9[k]);
    }
    float2 r = bmm256(mn, mx, sh);
    {
        float sc = fmaxf((r.y - r.x) / QMAX_, 1e-8f);
#pragma unroll
        for (int k = 0; k < 9; k++) g_qdw[t * 9 + k] = quantf(w9[k], r.x, sc);
    }
    // depthwise bias
    {
        float v = dw_b[t];
        float2 rb = bmm256(v, v, sh);
        float sc = fmaxf((rb.y - rb.x) / QMAX_, 1e-8f);
        g_qdwb[t] = quantf(v, rb.x, sc);
    }
    // bn1_w
    {
        float v = bn1_w[t];
        float2 rb = bmm256(v, v, sh);
        float sc = fmaxf((rb.y - rb.x) / QMAX_, 1e-8f);
        g_qbn1w[t] = quantf(v, rb.x, sc);
    }
    // bn2_w
    {
        float v = bn2_w[t];
        float2 rb = bmm256(v, v, sh);
        float sc = fmaxf((rb.y - rb.x) / QMAX_, 1e-8f);
        g_qbn2w[t] = quantf(v, rb.x, sc);
    }
    __syncthreads();
    // pack pointwise weight indices [k=c/4][o] + suma per o
    {
        int o = t;
        float wmn = s_wmn, wsc = s_wsc;
        float winv = 1.f / wsc;
        unsigned int suma = 0;
#pragma unroll 4
        for (int k = 0; k < 64; k++) {
            float4 w = *reinterpret_cast<const float4*>(&pw[o * C_ + 4 * k]);
            float ws[4] = {w.x, w.y, w.z, w.w};
            unsigned int pk = 0;
#pragma unroll
            for (int j = 0; j < 4; j++) {
                float u = (ws[j] - wmn) * winv;
                u = fminf(fmaxf(u, 0.f), QMAX_);
                pk |= ((unsigned int)(int)rintf(u)) << (8 * j);
            }
            g_apk[k * C_ + o] = pk;
            suma = __dp4a(pk, 0x01010101u, suma);
        }
        g_suma[o] = (float)suma;
    }
}

// Spacer: idempotent re-zero of isum (also a cheap way to land conv at launch index 3).
__global__ void spacer_kernel() {
    int i = threadIdx.x;
    if (i < C_) { g_isum1[i] = 0; g_isum2[i] = 0; }
}

// Depthwise 3x3, pad 1. One block per (s,c) plane. Vertical 4-output strips:
// 18 tap loads per 4 outputs, no per-pixel divides, stride-1 smem access.
__global__ __launch_bounds__(256) void conv_kernel(const float* __restrict__ x) {
    int c = blockIdx.x, s = blockIdx.y;
    __shared__ float tile[58 * 58];
    __shared__ float sh[16];
    const float mn0 = g_mn[0], s0 = g_sc[0], i0 = g_inv[0];
    const float* xp = x + ((size_t)s * C_ + c) * HW_;
    int t = threadIdx.x;
    for (int i = t; i < 58 * 58; i += 256) {
        int r = i / 58, q = i - r * 58;
        int gy = r - 1, gx = q - 1;
        float v = 0.f;  // zero padding is NOT quantized
        if ((unsigned)gy < 56u && (unsigned)gx < 56u) {
            float u = (xp[gy * 56 + gx] - mn0) * i0;
            u = fminf(fmaxf(u, 0.f), QMAX_);
            v = rintf(u) * s0 + mn0;
        }
        tile[i] = v;
    }
    float w[9];
#pragma unroll
    for (int k = 0; k < 9; k++) w[k] = g_qdw[c * 9 + k];
    float bias = g_qdwb[c];
    __syncthreads();
    float* hp = h1_buf + ((size_t)s * C_ + c) * HW_;
    float mn = FINF, mx = -FINF;
    // 784 strips: gx = st % 56, row group rg = st / 56, output rows 4rg..4rg+3
    for (int st = t; st < 784; st += 256) {
        int gx = st % 56, rg = st / 56;
        int y0 = rg * 4;
        const float* tp = tile + y0 * 58 + gx;
        float a[6][3];
#pragma unroll
        for (int r6 = 0; r6 < 6; r6++) {
            a[r6][0] = tp[r6 * 58];
            a[r6][1] = tp[r6 * 58 + 1];
            a[r6][2] = tp[r6 * 58 + 2];
        }
#pragma unroll
        for (int r4 = 0; r4 < 4; r4++) {
            float acc = bias;
            acc += a[r4][0] * w[0] + a[r4][1] * w[1] + a[r4][2] * w[2];
            acc += a[r4 + 1][0] * w[3] + a[r4 + 1][1] * w[4] + a[r4 + 1][2] * w[5];
            acc += a[r4 + 2][0] * w[6] + a[r4 + 2][1] * w[7] + a[r4 + 2][2] * w[8];
            hp[(y0 + r4) * 56 + gx] = acc;
            mn = fminf(mn, acc); mx = fmaxf(mx, acc);
        }
    }
    float2 r = bmm256(mn, mx, sh);
    if (t == 0) { g_h1_min[s * C_ + c] = r.x; g_h1_max[s * C_ + c] = r.y; }
}

// stage 0: h1 stats -> g_mn[1],g_sc[1], A1 ; stage 1: h3 stats -> g_mn[3],g_sc[3], A2
__global__ __launch_bounds__(256) void prep_stats_kernel(int stage) {
    int t = threadIdx.x;
    const float* MN  = stage ? g_h3_min : g_h1_min;
    const float* MX  = stage ? g_h3_max : g_h1_max;
    const float* QBW = stage ? g_qbn2w : g_qbn1w;
    float* A = stage ? g_A2 : g_A1;
    int qi = stage ? 3 : 1;

    __shared__ float pmn[256], pmx[256];
    __shared__ float smn[B_], smx[B_];
    __shared__ float s_mn, s_s;
    {
        int s = t >> 3, j = t & 7;
        float mn = FINF, mx = -FINF;
        for (int c = j * 32; c < j * 32 + 32; c++) {
            mn = fminf(mn, MN[s * C_ + c]);
            mx = fmaxf(mx, MX[s * C_ + c]);
        }
        pmn[t] = mn; pmx[t] = mx;
    }
    __syncthreads();
    if (t < B_) {
        float mn = FINF, mx = -FINF;
#pragma unroll
        for (int j = 0; j < 8; j++) {
            mn = fminf(mn, pmn[t * 8 + j]);
            mx = fmaxf(mx, pmx[t * 8 + j]);
        }
        smn[t] = mn; smx[t] = mx;
    }
    __syncthreads();
    if (t == 0) {
        float a = 0.f, b = 0.f;
        for (int s = 0; s < B_; s++) { a += smn[s]; b += smx[s]; }
        float mn = a / 32.f, mx = b / 32.f;
        s_mn = mn;
        s_s = fmaxf((mx - mn) / QMAX_, 1e-8f);
        g_mn[qi] = s_mn; g_sc[qi] = s_s; g_inv[qi] = 1.f / s_s;
    }
    __syncthreads();
    float mn = s_mn, sv = s_s;

    float amax = 0.f, amin = 0.f;
    for (int j = 0; j < NCH_; j++) {
        float cmx = fmaxf(MX[(2 * j) * C_ + t], MX[(2 * j + 1) * C_ + t]);
        float cmn = fminf(MN[(2 * j) * C_ + t], MN[(2 * j + 1) * C_ + t]);
        amax += quantf(cmx, mn, sv);
        amin += quantf(cmn, mn, sv);
    }
    float mean_max = amax * (1.f / 16.f), mean_min = amin * (1.f / 16.f);
    double sfd = 0.175 * (1.0 + sqrt(3.141592653589793 * 1.3862943611198906))
               / sqrt(2.0 * log(6272.0));
    float sf = (float)sfd;
    float rs = 1.0f / ((mean_max - mean_min) * sf + 1e-5f);

    __shared__ float sh[16];
    float2 r = bmm256(rs, rs, sh);
    float rsc = fmaxf((r.y - r.x) / QMAX_, 1e-8f);
    float qs = quantf(rs, r.x, rsc);
    A[t] = qs * QBW[t];
}

// Stage0 quantize: read 4 channel planes of h1, write channel-packed u32 [s][k][p]
// into i_buf (u32 view), accumulate per-channel integer sums.
__global__ __launch_bounds__(256) void quantpack_kernel() {
    int k = blockIdx.x, s = blockIdx.y;
    int t = threadIdx.x;
    float mn = g_mn[1], iv = g_inv[1];
    const float4* h0 = reinterpret_cast<const float4*>(h1_buf + ((size_t)s * C_ + 4 * k + 0) * HW_);
    const float4* h1p = reinterpret_cast<const float4*>(h1_buf + ((size_t)s * C_ + 4 * k + 1) * HW_);
    const float4* h2 = reinterpret_cast<const float4*>(h1_buf + ((size_t)s * C_ + 4 * k + 2) * HW_);
    const float4* h3 = reinterpret_cast<const float4*>(h1_buf + ((size_t)s * C_ + 4 * k + 3) * HW_);
    uint4* op = reinterpret_cast<uint4*>(reinterpret_cast<unsigned int*>(i_buf) + ((size_t)s * 64 + k) * HW_);
    int sj[4] = {0, 0, 0, 0};
    for (int p = t; p < HW_ / 4; p += 256) {
        float4 v[4] = {h0[p], h1p[p], h2[p], h3[p]};
        unsigned int w[4] = {0u, 0u, 0u, 0u};   // per pixel (x,y,z,w)
#pragma unroll
        for (int j = 0; j < 4; j++) {
            float ux = fminf(fmaxf((v[j].x - mn) * iv, 0.f), QMAX_);
            float uy = fminf(fmaxf((v[j].y - mn) * iv, 0.f), QMAX_);
            float uz = fminf(fmaxf((v[j].z - mn) * iv, 0.f), QMAX_);
            float uw = fminf(fmaxf((v[j].w - mn) * iv, 0.f), QMAX_);
            int ix = (int)rintf(ux), iy = (int)rintf(uy), iz = (int)rintf(uz), iw = (int)rintf(uw);
            sj[j] += ix + iy + iz + iw;
            w[0] |= (unsigned int)ix << (8 * j);
            w[1] |= (unsigned int)iy << (8 * j);
            w[2] |= (unsigned int)iz << (8 * j);
            w[3] |= (unsigned int)iw << (8 * j);
        }
        op[p] = make_uint4(w[0], w[1], w[2], w[3]);
    }
    __shared__ int sw[8][4];
    int lane = t & 31, wid = t >> 5;
#pragma unroll
    for (int j = 0; j < 4; j++) {
#pragma unroll
        for (int o = 16; o > 0; o >>= 1) sj[j] += __shfl_xor_sync(0xffffffffu, sj[j], o);
        if (lane == 0) sw[wid][j] = sj[j];
    }
    __syncthreads();
    if (t < 4) {
        int tot = 0;
#pragma unroll
        for (int i = 0; i < 8; i++) tot += sw[i][t];
        atomicAdd(&g_isum1[4 * k + t], tot);
    }
}

// stage 0: C1 from isum1 + derive h2 quantizer (mn2/s2) + build i->b LUT. stage 1: C2 from isum2.
__global__ __launch_bounds__(256) void prep_mean_kernel(int stage, const float* __restrict__ bias) {
    int t = threadIdx.x;
    const float* A = stage ? g_A2 : g_A1;
    float* Cc = stage ? g_C2 : g_C1;
    float mnq = g_mn[stage ? 3 : 1], sq = g_sc[stage ? 3 : 1];
    int isum = stage ? g_isum2[t] : g_isum1[t];
    float mean = mnq + sq * ((float)isum * (1.0f / 100352.0f));
    Cc[t] = bias[t] - mean * A[t];
    if (stage == 0) {
        __syncthreads();
        float mn1 = g_mn[1], s1 = g_sc[1];
        __shared__ float pmn[256], pmx[256];
        __shared__ float smn[B_], smx[B_];
        {
            int s = t >> 3, j = t & 7;
            float lo = FINF, hi = -FINF;
            for (int c = j * 32; c < j * 32 + 32; c++) {
                float Aa = g_A1[c], Cv = g_C1[c];
                float v1 = Aa * quantf(g_h1_max[s * C_ + c], mn1, s1) + Cv;
                float v2 = Aa * quantf(g_h1_min[s * C_ + c], mn1, s1) + Cv;
                hi = fmaxf(hi, fmaxf(fmaxf(v1, v2), 0.f));
                lo = fminf(lo, fmaxf(fminf(v1, v2), 0.f));
            }
            pmn[t] = lo; pmx[t] = hi;
        }
        __syncthreads();
        if (t < B_) {
            float lo = FINF, hi = -FINF;
#pragma unroll
            for (int j = 0; j < 8; j++) {
                lo = fminf(lo, pmn[t * 8 + j]);
                hi = fmaxf(hi, pmx[t * 8 + j]);
            }
            smn[t] = lo; smx[t] = hi;
        }
        __syncthreads();
        if (t == 0) {
            float a = 0.f, b = 0.f;
            for (int s = 0; s < B_; s++) { a += smn[s]; b += smx[s]; }
            float mn2 = a / 32.f, mx2 = b / 32.f;
            g_mn[2] = mn2;
            g_sc[2] = fmaxf((mx2 - mn2) / QMAX_, 1e-8f);
        }
        __syncthreads();
        // Build per-channel LUT: i -> b index of quantized h2
        float mn2 = g_mn[2], s2v = g_sc[2];
        float inv2 = 1.f / s2v;
        float Aa = g_A1[t], Cv = g_C1[t];
        for (int i = 0; i < 256; i++) {
            float q1 = mn1 + (float)i * s1;
            float h2 = fmaxf(Aa * q1 + Cv, 0.f);
            float u = (h2 - mn2) * inv2;
            u = fminf(fmaxf(u, 0.f), QMAX_);
            g_lut[t * 256 + i] = (unsigned char)(int)rintf(u);
        }
    }
}

// Exact integer pointwise GEMM via dp4a, with fused LUT remap of B on load.
// Tile: 128 o x 64 p, K=256 (64 packs) fully resident. Dynamic smem 49408 B.
__global__ __launch_bounds__(256) void gemm_kernel(float* __restrict__ out) {
    extern __shared__ unsigned int dyn[];
    unsigned int* As = dyn;                  // [64][128]
    unsigned int* Bs = dyn + 64 * 128;       // [64][64]
    unsigned int* sbu = dyn + 64 * 128 + 64 * 64;  // [64] per-pixel b-sum
    int s = blockIdx.z;
    int om = blockIdx.y * 128;
    int pn = blockIdx.x * 64;
    int tid = threadIdx.x;
    if (tid < 64) sbu[tid] = 0u;
#pragma unroll
    for (int j = 0; j < 32; j++) {
        int e = tid + 256 * j;
        int k = e >> 7, m = e & 127;
        As[k * 128 + m] = g_apk[k * C_ + om + m];
    }
    const unsigned int* ipk = reinterpret_cast<const unsigned int*>(i_buf) + (size_t)s * 64 * HW_;
#pragma unroll
    for (int j = 0; j < 16; j++) {
        int e = tid + 256 * j;
        int k = e >> 6, p = e & 63;
        unsigned int w = ipk[k * HW_ + pn + p];
        const unsigned char* lp = g_lut + k * 1024;
        unsigned int b0 = lp[w & 255];
        unsigned int b1 = lp[256 + ((w >> 8) & 255)];
        unsigned int b2 = lp[512 + ((w >> 16) & 255)];
        unsigned int b3 = lp[768 + (w >> 24)];
        Bs[k * 64 + p] = b0 | (b1 << 8) | (b2 << 16) | (b3 << 24);
    }
    __syncthreads();
    // per-pixel sum of b over all 256 channels: 4 partials of 16 k each
    {
        int p = tid & 63, q = tid >> 6;
        unsigned int ssum = 0;
#pragma unroll
        for (int k = 16 * q; k < 16 * q + 16; k++) ssum = __dp4a(Bs[k * 64 + p], 0x01010101u, ssum);
        atomicAdd(&sbu[p], ssum);
    }
    __syncthreads();

    int tx = tid & 15, ty = tid >> 4;
    unsigned int acc[8][4];
#pragma unroll
    for (int i = 0; i < 8; i++)
#pragma unroll
        for (int j = 0; j < 4; j++) acc[i][j] = 0u;

#pragma unroll 8
    for (int k = 0; k < 64; k++) {
        uint4 a0 = *reinterpret_cast<const uint4*>(&As[k * 128 + ty * 8]);
        uint4 a1 = *reinterpret_cast<const uint4*>(&As[k * 128 + ty * 8 + 4]);
        uint4 bv = *reinterpret_cast<const uint4*>(&Bs[k * 64 + tx * 4]);
        unsigned int a[8] = {a0.x, a0.y, a0.z, a0.w, a1.x, a1.y, a1.z, a1.w};
        unsigned int b[4] = {bv.x, bv.y, bv.z, bv.w};
#pragma unroll
        for (int i = 0; i < 8; i++)
#pragma unroll
            for (int j = 0; j < 4; j++)
                acc[i][j] = __dp4a(a[i], b[j], acc[i][j]);
    }

    float wmn = g_pw_mn, sw = g_pw_sc;
    float mn2 = g_mn[2], s2 = g_sc[2];
    float c0 = sw * s2;
    float cb = wmn * s2;
    float ca = mn2 * sw;
    float kconst = 256.f * wmn * mn2;
    float sb[4];
#pragma unroll
    for (int j = 0; j < 4; j++) sb[j] = (float)sbu[tx * 4 + j];

#pragma unroll
    for (int i = 0; i < 8; i++) {
        int o = om + ty * 8 + i;
        float base = ca * g_suma[o] + kconst;
        float r0 = c0 * (float)acc[i][0] + cb * sb[0] + base;
        float r1 = c0 * (float)acc[i][1] + cb * sb[1] + base;
        float r2 = c0 * (float)acc[i][2] + cb * sb[2] + base;
        float r3 = c0 * (float)acc[i][3] + cb * sb[3] + base;
        float4 v = make_float4(r0, r1, r2, r3);
        *reinterpret_cast<float4*>(&out[((size_t)s * C_ + o) * HW_ + pn + tx * 4]) = v;
        float lmn = fminf(fminf(r0, r1), fminf(r2, r3));
        float lmx = fmaxf(fmaxf(r0, r1), fmaxf(r2, r3));
#pragma unroll
        for (int off = 8; off > 0; off >>= 1) {
            lmn = fminf(lmn, __shfl_down_sync(0xffffffffu, lmn, off, 16));
            lmx = fmaxf(lmx, __shfl_down_sync(0xffffffffu, lmx, off, 16));
        }
        if (tx == 0) {
            atomicMinF(&g_h3_min[s * C_ + o], lmn);
            atomicMaxF(&g_h3_max[s * C_ + o], lmx);
        }
    }
}

// Stage1 quantize: read h3 (=out), write u8 indices linear + per-channel integer sums.
__global__ __launch_bounds__(256) void quantsum_kernel(const float* __restrict__ ext) {
    int c = blockIdx.x, s = blockIdx.y;
    float mn = g_mn[3], iv = g_inv[3];
    const float4* hp = reinterpret_cast<const float4*>(ext + ((size_t)s * C_ + c) * HW_);
    uchar4* op = reinterpret_cast<uchar4*>(i_buf + ((size_t)s * C_ + c) * HW_);
    int acc = 0;
    for (int p = threadIdx.x; p < HW_ / 4; p += 256) {
        float4 v = hp[p];
        float tx = fminf(fmaxf((v.x - mn) * iv, 0.f), QMAX_);
        float ty = fminf(fmaxf((v.y - mn) * iv, 0.f), QMAX_);
        float tz = fminf(fmaxf((v.z - mn) * iv, 0.f), QMAX_);
        float tw = fminf(fmaxf((v.w - mn) * iv, 0.f), QMAX_);
        int ix = (int)rintf(tx), iy = (int)rintf(ty), iz = (int)rintf(tz), iw = (int)rintf(tw);
        acc += ix + iy + iz + iw;
        op[p] = make_uchar4((unsigned char)ix, (unsigned char)iy, (unsigned char)iz, (unsigned char)iw);
    }
#pragma unroll
    for (int o = 16; o > 0; o >>= 1) acc += __shfl_xor_sync(0xffffffffu, acc, o);
    __shared__ int sd[8];
    int lane = threadIdx.x & 31, wid = threadIdx.x >> 5;
    if (lane == 0) sd[wid] = acc;
    __syncthreads();
    if (threadIdx.x == 0) {
        int tot = 0;
#pragma unroll
        for (int i = 0; i < 8; i++) tot += sd[i];
        atomicAdd(&g_isum2[c], tot);
    }
}

// Final range_bn + relu: read u8 indices, write fp32 out.
__global__ __launch_bounds__(256) void final_kernel(float4* __restrict__ out) {
    const float mn3 = g_mn[3], s3 = g_sc[3];
    const uchar4* ib = reinterpret_cast<const uchar4*>(i_buf);
    size_t stride = (size_t)gridDim.x * blockDim.x;
    for (size_t i = (size_t)blockIdx.x * blockDim.x + threadIdx.x; i < TOT_ / 4; i += stride) {
        int plane = (int)(i / (HW_ / 4));   // s*256 + o  (3136 % 4 == 0)
        int o = plane & 255;
        float A = g_A2[o], Cv = g_C2[o];
        uchar4 q = ib[i];
        float4 v;
        v.x = fmaxf(A * (mn3 + (float)q.x * s3) + Cv, 0.f);
        v.y = fmaxf(A * (mn3 + (float)q.y * s3) + Cv, 0.f);
        v.z = fmaxf(A * (mn3 + (float)q.z * s3) + Cv, 0.f);
        v.w = fmaxf(A * (mn3 + (float)q.w * s3) + Cv, 0.f);
        out[i] = v;
    }
}

extern "C" void kernel_launch(void* const* d_in, const int* in_sizes, int n_in,
                              void* d_out, int out_size) {
    const float* x     = (const float*)d_in[0];
    const float* dw_w  = (const float*)d_in[1];
    const float* dw_b  = (const float*)d_in[2];
    const float* bn1_w = (const float*)d_in[3];
    const float* bn1_b = (const float*)d_in[4];
    const float* pw_w  = (const float*)d_in[5];
    const float* bn2_w = (const float*)d_in[6];
    const float* bn2_b = (const float*)d_in[7];
    float* out = (float*)d_out;

    static int smem_set = 0;
    if (!smem_set) {
        cudaFuncSetAttribute(gemm_kernel, cudaFuncAttributeMaxDynamicSharedMemorySize, 49664);
        smem_set = 1;
    }

    init_x_kernel<<<1632, 256>>>(x, pw_w);                    // 0
    prep1_kernel<<<1, 256>>>(dw_w, dw_b, bn1_w, bn2_w, pw_w); // 1
    spacer_kernel<<<1, 256>>>();                              // 2
    conv_kernel<<<dim3(C_, B_), 256>>>(x);                    // 3  <- ncu slot
    prep_stats_kernel<<<1, 256>>>(0);                         // 4
    quantpack_kernel<<<dim3(64, B_), 256>>>();                // 5
    prep_mean_kernel<<<1, 256>>>(0, bn1_b);                   // 6
    gemm_kernel<<<dim3(HW_ / 64, 2, B_), 256, 49664>>>(out);  // 7
    prep_stats_kernel<<<1, 256>>>(1);                         // 8
    quantsum_kernel<<<dim3(C_, B_), 256>>>(out);              // 9
    prep_mean_kernel<<<1, 256>>>(1, bn2_b);                   // 10
    final_kernel<<<4096, 256>>>((float4*)out);                // 11
}

// round 9
// speedup vs baseline: 3.3324x; 1.2484x over previous
#include <cuda_runtime.h>
#include <cuda_bf16.h>
#include <math.h>
#include <stdint.h>

// Problem constants
#define B_    32
#define C_    256
#define H_    56
#define W_    56
#define HW_   3136
#define CHW_  802816      // 256*3136
#define TOT_  25690112    // 32*256*3136
#define NCH_  16          // chunks
#define QMAX_ 255.0f

#define FINF __int_as_float(0x7f800000)

// GEMM config: block tile M=256 (all outputs) x N=128 px x K=256, 512 threads, mma.sync bf16
#define GP    128
#define NPTG  25          // ceil(3136/128)
#define AW    132         // smem row stride in words (528 bytes) -> conflict-free fragments
#define SMB_OFF (256 * 528)            // 135168
#define SMS_OFF (SMB_OFF + 128 * 528)  // 202752
#define SMT_G   (SMS_OFF + 512)        // 203264

// ---------------- device globals (scratch; no allocations allowed) ----------------
__device__ float h1_buf[TOT_];                  // depthwise conv output (103 MB)
__device__ unsigned char i_buf[TOT_];           // stage0: packed u32 [s][k][p]; stage1: u8 [s][c][p]
__device__ unsigned short g_aimg16[C_ * C_];    // bf16 weight-index image [o][c]

__device__ float g_x_smin[B_], g_x_smax[B_];
__device__ float g_h1_min[B_ * C_], g_h1_max[B_ * C_];   // per (s,c)
__device__ float g_h3_min[B_ * C_], g_h3_max[B_ * C_];   // per (s,o)
__device__ int   g_isum1[C_], g_isum2[C_];
__device__ float g_pw_pmn[32], g_pw_pmx[32];
__device__ float g_pw_mn, g_pw_sc;

__device__ float g_mn[4], g_sc[4], g_inv[4];    // 0:x 1:h1 2:h2 3:h3 quantizer params
__device__ float g_qdw[C_ * 9], g_qdwb[C_], g_qbn1w[C_], g_qbn2w[C_];
__device__ unsigned int g_apk[64 * C_];    // packed weight indices [k=c/4][o]
__device__ float g_suma[C_];               // sum over c of a-index per o
__device__ unsigned int g_lut32[C_ * 256]; // per-channel i -> (bf16(b) | b<<16)
__device__ float g_A1[C_], g_C1[C_], g_A2[C_], g_C2[C_];

// ---------------- helpers ----------------
__device__ __forceinline__ float quantf(float v, float mn, float sc) {
    float t = (v - mn) / sc;
    t = fminf(fmaxf(t, 0.f), QMAX_);
    return rintf(t) * sc + mn;
}
__device__ __forceinline__ void atomicMaxF(float* a, float v) {
    if (v >= 0.f) atomicMax((int*)a, __float_as_int(v));
    else          atomicMin((unsigned int*)a, __float_as_uint(v));
}
__device__ __forceinline__ void atomicMinF(float* a, float v) {
    if (v >= 0.f) atomicMin((int*)a, __float_as_int(v));
    else          atomicMax((unsigned int*)a, __float_as_uint(v));
}
__device__ float2 bmm256(float mn, float mx, float* sh) {
    int t = threadIdx.x, lane = t & 31, wid = t >> 5;
#pragma unroll
    for (int o = 16; o > 0; o >>= 1) {
        mn = fminf(mn, __shfl_xor_sync(0xffffffffu, mn, o));
        mx = fmaxf(mx, __shfl_xor_sync(0xffffffffu, mx, o));
    }
    __syncthreads();
    if (lane == 0) { sh[wid] = mn; sh[8 + wid] = mx; }
    __syncthreads();
    float rmn = FINF, rmx = -FINF;
#pragma unroll
    for (int i = 0; i < 8; i++) { rmn = fminf(rmn, sh[i]); rmx = fmaxf(rmx, sh[8 + i]); }
    return make_float2(rmn, rmx);
}

// ---------------- kernels ----------------
__global__ __launch_bounds__(256) void init_x_kernel(const float* __restrict__ x,
                                                     const float* __restrict__ pw) {
    int b = blockIdx.x;
    if (b < 32) {
        int i = b * 256 + threadIdx.x;
        g_h3_min[i] = FINF; g_h3_max[i] = -FINF;
        if (i < C_) { g_isum1[i] = 0; g_isum2[i] = 0; }
        if (i < B_) { g_x_smin[i] = FINF; g_x_smax[i] = -FINF; }
    } else if (b < 64) {
        int pb = b - 32;
        const float4* p4 = reinterpret_cast<const float4*>(pw);
        float mn = FINF, mx = -FINF;
        for (int i = pb * 512 + threadIdx.x; i < (pb + 1) * 512; i += 256) {
            float4 v = p4[i];
            mn = fminf(fminf(mn, fminf(v.x, v.y)), fminf(v.z, v.w));
            mx = fmaxf(fmaxf(mx, fmaxf(v.x, v.y)), fmaxf(v.z, v.w));
        }
        __shared__ float sh[16];
        float2 r = bmm256(mn, mx, sh);
        if (threadIdx.x == 0) { g_pw_pmn[pb] = r.x; g_pw_pmx[pb] = r.y; }
    } else {
        int b2 = b - 64;
        int s = b2 / 49, blk = b2 % 49;
        const float4* xp = reinterpret_cast<const float4*>(x + (size_t)s * CHW_);
        float mn = FINF, mx = -FINF;
        for (int i = blk * 256 + threadIdx.x; i < CHW_ / 4; i += 49 * 256) {
            float4 v = xp[i];
            mn = fminf(fminf(mn, fminf(v.x, v.y)), fminf(v.z, v.w));
            mx = fmaxf(fmaxf(mx, fmaxf(v.x, v.y)), fmaxf(v.z, v.w));
        }
        __shared__ float sh[16];
        float2 r = bmm256(mn, mx, sh);
        if (threadIdx.x == 0) { atomicMinF(&g_x_smin[s], r.x); atomicMaxF(&g_x_smax[s], r.y); }
    }
}

__global__ __launch_bounds__(256) void prep1_kernel(const float* __restrict__ dw_w,
                                                    const float* __restrict__ dw_b,
                                                    const float* __restrict__ bn1_w,
                                                    const float* __restrict__ bn2_w,
                                                    const float* __restrict__ pw) {
    __shared__ float sh[16];
    __shared__ float s_wmn, s_wsc;
    int t = threadIdx.x;
    if (t == 0) {
        float a = 0.f, b = 0.f;
        for (int s = 0; s < B_; s++) { a += g_x_smin[s]; b += g_x_smax[s]; }
        float mn = a / 32.f, mx = b / 32.f;
        g_mn[0] = mn;
        float sc = fmaxf((mx - mn) / QMAX_, 1e-8f);
        g_sc[0] = sc; g_inv[0] = 1.f / sc;
    } else if (t == 32) {
        float mn = FINF, mx = -FINF;
        for (int i = 0; i < 32; i++) { mn = fminf(mn, g_pw_pmn[i]); mx = fmaxf(mx, g_pw_pmx[i]); }
        float sc = fmaxf((mx - mn) / QMAX_, 1e-8f);
        g_pw_mn = mn; g_pw_sc = sc;
        s_wmn = mn; s_wsc = sc;
    }
    float w9[9];
    float mn = FINF, mx = -FINF;
#pragma unroll
    for (int k = 0; k < 9; k++) {
        w9[k] = dw_w[t * 9 + k];
        mn = fminf(mn, w9[k]); mx = fmaxf(mx, w9[k]);
    }
    float2 r = bmm256(mn, mx, sh);
    {
        float sc = fmaxf((r.y - r.x) / QMAX_, 1e-8f);
#pragma unroll
        for (int k = 0; k < 9; k++) g_qdw[t * 9 + k] = quantf(w9[k], r.x, sc);
    }
    {
        float v = dw_b[t];
        float2 rb = bmm256(v, v, sh);
        float sc = fmaxf((rb.y - rb.x) / QMAX_, 1e-8f);
        g_qdwb[t] = quantf(v, rb.x, sc);
    }
    {
        float v = bn1_w[t];
        float2 rb = bmm256(v, v, sh);
        float sc = fmaxf((rb.y - rb.x) / QMAX_, 1e-8f);
        g_qbn1w[t] = quantf(v, rb.x, sc);
    }
    {
        float v = bn2_w[t];
        float2 rb = bmm256(v, v, sh);
        float sc = fmaxf((rb.y - rb.x) / QMAX_, 1e-8f);
        g_qbn2w[t] = quantf(v, rb.x, sc);
    }
    __syncthreads();
    {
        int o = t;
        float wmn = s_wmn, winv = 1.f / s_wsc;
        unsigned int suma = 0;
#pragma unroll 4
        for (int k = 0; k < 64; k++) {
            float4 w = *reinterpret_cast<const float4*>(&pw[o * C_ + 4 * k]);
            float ws[4] = {w.x, w.y, w.z, w.w};
            unsigned int pk = 0;
#pragma unroll
            for (int j = 0; j < 4; j++) {
                float u = (ws[j] - wmn) * winv;
                u = fminf(fmaxf(u, 0.f), QMAX_);
                pk |= ((unsigned int)(int)rintf(u)) << (8 * j);
            }
            g_apk[k * C_ + o] = pk;
            suma = __dp4a(pk, 0x01010101u, suma);
        }
        g_suma[o] = (float)suma;
    }
}

// Build plain bf16 weight-index image [o][c].
__global__ __launch_bounds__(256) void prep_wbf_kernel() {
    int o = blockIdx.x;
    int c = threadIdx.x;
    unsigned int a = (g_apk[(c >> 2) * C_ + o] >> (8 * (c & 3))) & 255u;
    __nv_bfloat16 bf = __float2bfloat16((float)a);
    g_aimg16[o * C_ + c] = *reinterpret_cast<unsigned short*>(&bf);
}

// Depthwise 3x3, pad 1. One block per (s,c) plane (R3-proven loop, fp32 stores).
__global__ __launch_bounds__(256) void conv_kernel(const float* __restrict__ x) {
    int c = blockIdx.x, s = blockIdx.y;
    __shared__ float tile[58 * 58];
    __shared__ float sh[16];
    const float mn0 = g_mn[0], s0 = g_sc[0], i0 = g_inv[0];
    const float* xp = x + ((size_t)s * C_ + c) * HW_;
    int t = threadIdx.x;
    for (int i = t; i < 58 * 58; i += 256) {
        int r = i / 58, q = i - r * 58;
        int gy = r - 1, gx = q - 1;
        float v = 0.f;  // zero padding is NOT quantized
        if ((unsigned)gy < 56u && (unsigned)gx < 56u) {
            float u = (xp[gy * 56 + gx] - mn0) * i0;
            u = fminf(fmaxf(u, 0.f), QMAX_);
            v = rintf(u) * s0 + mn0;
        }
        tile[i] = v;
    }
    float w[9];
#pragma unroll
    for (int k = 0; k < 9; k++) w[k] = g_qdw[c * 9 + k];
    float bias = g_qdwb[c];
    __syncthreads();
    float* hp = h1_buf + ((size_t)s * C_ + c) * HW_;
    float mn = FINF, mx = -FINF;
    for (int p = t; p < HW_; p += 256) {
        int yy = p / 56, xx = p - yy * 56;
        const float* tp = tile + yy * 58 + xx;
        float acc = bias;
        acc += tp[0] * w[0] + tp[1] * w[1] + tp[2] * w[2];
        acc += tp[58] * w[3] + tp[59] * w[4] + tp[60] * w[5];
        acc += tp[116] * w[6] + tp[117] * w[7] + tp[118] * w[8];
        hp[p] = acc;
        mn = fminf(mn, acc); mx = fmaxf(mx, acc);
    }
    float2 r = bmm256(mn, mx, sh);
    if (t == 0) { g_h1_min[s * C_ + c] = r.x; g_h1_max[s * C_ + c] = r.y; }
}

__global__ __launch_bounds__(256) void prep_stats_kernel(int stage) {
    int t = threadIdx.x;
    const float* MN  = stage ? g_h3_min : g_h1_min;
    const float* MX  = stage ? g_h3_max : g_h1_max;
    const float* QBW = stage ? g_qbn2w : g_qbn1w;
    float* A = stage ? g_A2 : g_A1;
    int qi = stage ? 3 : 1;

    __shared__ float pmn[256], pmx[256];
    __shared__ float smn[B_], smx[B_];
    __shared__ float s_mn, s_s;
    {
        int s = t >> 3, j = t & 7;
        float mn = FINF, mx = -FINF;
        for (int c = j * 32; c < j * 32 + 32; c++) {
            mn = fminf(mn, MN[s * C_ + c]);
            mx = fmaxf(mx, MX[s * C_ + c]);
        }
        pmn[t] = mn; pmx[t] = mx;
    }
    __syncthreads();
    if (t < B_) {
        float mn = FINF, mx = -FINF;
#pragma unroll
        for (int j = 0; j < 8; j++) {
            mn = fminf(mn, pmn[t * 8 + j]);
            mx = fmaxf(mx, pmx[t * 8 + j]);
        }
        smn[t] = mn; smx[t] = mx;
    }
    __syncthreads();
    if (t == 0) {
        float a = 0.f, b = 0.f;
        for (int s = 0; s < B_; s++) { a += smn[s]; b += smx[s]; }
        float mn = a / 32.f, mx = b / 32.f;
        s_mn = mn;
        s_s = fmaxf((mx - mn) / QMAX_, 1e-8f);
        g_mn[qi] = s_mn; g_sc[qi] = s_s; g_inv[qi] = 1.f / s_s;
    }
    __syncthreads();
    float mn = s_mn, sv = s_s;

    float amax = 0.f, amin = 0.f;
    for (int j = 0; j < NCH_; j++) {
        float cmx = fmaxf(MX[(2 * j) * C_ + t], MX[(2 * j + 1) * C_ + t]);
        float cmn = fminf(MN[(2 * j) * C_ + t], MN[(2 * j + 1) * C_ + t]);
        amax += quantf(cmx, mn, sv);
        amin += quantf(cmn, mn, sv);
    }
    float mean_max = amax * (1.f / 16.f), mean_min = amin * (1.f / 16.f);
    double sfd = 0.175 * (1.0 + sqrt(3.141592653589793 * 1.3862943611198906))
               / sqrt(2.0 * log(6272.0));
    float sf = (float)sfd;
    float rs = 1.0f / ((mean_max - mean_min) * sf + 1e-5f);

    __shared__ float sh[16];
    float2 r = bmm256(rs, rs, sh);
    float rsc = fmaxf((r.y - r.x) / QMAX_, 1e-8f);
    float qs = quantf(rs, r.x, rsc);
    A[t] = qs * QBW[t];
}

// Stage0 quantize: read 4 fp32 channel planes of h1, write channel-packed u32 [s][k][p].
__global__ __launch_bounds__(256) void quantpack_kernel() {
    int k = blockIdx.x, s = blockIdx.y;
    int t = threadIdx.x;
    float mn = g_mn[1], iv = g_inv[1];
    const float4* h0 = reinterpret_cast<const float4*>(h1_buf + ((size_t)s * C_ + 4 * k + 0) * HW_);
    const float4* h1p = reinterpret_cast<const float4*>(h1_buf + ((size_t)s * C_ + 4 * k + 1) * HW_);
    const float4* h2 = reinterpret_cast<const float4*>(h1_buf + ((size_t)s * C_ + 4 * k + 2) * HW_);
    const float4* h3 = reinterpret_cast<const float4*>(h1_buf + ((size_t)s * C_ + 4 * k + 3) * HW_);
    uint4* op = reinterpret_cast<uint4*>(reinterpret_cast<unsigned int*>(i_buf) + ((size_t)s * 64 + k) * HW_);
    int sj[4] = {0, 0, 0, 0};
    for (int p = t; p < HW_ / 4; p += 256) {
        float4 v[4] = {h0[p], h1p[p], h2[p], h3[p]};
        unsigned int w[4] = {0u, 0u, 0u, 0u};
#pragma unroll
        for (int j = 0; j < 4; j++) {
            float ux = fminf(fmaxf((v[j].x - mn) * iv, 0.f), QMAX_);
            float uy = fminf(fmaxf((v[j].y - mn) * iv, 0.f), QMAX_);
            float uz = fminf(fmaxf((v[j].z - mn) * iv, 0.f), QMAX_);
            float uw = fminf(fmaxf((v[j].w - mn) * iv, 0.f), QMAX_);
            int ix = (int)rintf(ux), iy = (int)rintf(uy), iz = (int)rintf(uz), iw = (int)rintf(uw);
            sj[j] += ix + iy + iz + iw;
            w[0] |= (unsigned int)ix << (8 * j);
            w[1] |= (unsigned int)iy << (8 * j);
            w[2] |= (unsigned int)iz << (8 * j);
            w[3] |= (unsigned int)iw << (8 * j);
        }
        op[p] = make_uint4(w[0], w[1], w[2], w[3]);
    }
    __shared__ int sw[8][4];
    int lane = t & 31, wid = t >> 5;
#pragma unroll
    for (int j = 0; j < 4; j++) {
#pragma unroll
        for (int o = 16; o > 0; o >>= 1) sj[j] += __shfl_xor_sync(0xffffffffu, sj[j], o);
        if (lane == 0) sw[wid][j] = sj[j];
    }
    __syncthreads();
    if (t < 4) {
        int tot = 0;
#pragma unroll
        for (int i = 0; i < 8; i++) tot += sw[i][t];
        atomicAdd(&g_isum1[4 * k + t], tot);
    }
}

// stage 0: C1 + h2 quantizer + combined LUT (bf16 bits | b<<16). stage 1: C2.
__global__ __launch_bounds__(256) void prep_mean_kernel(int stage, const float* __restrict__ bias) {
    int t = threadIdx.x;
    const float* A = stage ? g_A2 : g_A1;
    float* Cc = stage ? g_C2 : g_C1;
    float mnq = g_mn[stage ? 3 : 1], sq = g_sc[stage ? 3 : 1];
    int isum = stage ? g_isum2[t] : g_isum1[t];
    float mean = mnq + sq * ((float)isum * (1.0f / 100352.0f));
    Cc[t] = bias[t] - mean * A[t];
    if (stage == 0) {
        __syncthreads();
        float mn1 = g_mn[1], s1 = g_sc[1];
        __shared__ float pmn[256], pmx[256];
        __shared__ float smn[B_], smx[B_];
        {
            int s = t >> 3, j = t & 7;
            float lo = FINF, hi = -FINF;
            for (int c = j * 32; c < j * 32 + 32; c++) {
                float Aa = g_A1[c], Cv = g_C1[c];
                float v1 = Aa * quantf(g_h1_max[s * C_ + c], mn1, s1) + Cv;
                float v2 = Aa * quantf(g_h1_min[s * C_ + c], mn1, s1) + Cv;
                hi = fmaxf(hi, fmaxf(fmaxf(v1, v2), 0.f));
                lo = fminf(lo, fmaxf(fminf(v1, v2), 0.f));
            }
            pmn[t] = lo; pmx[t] = hi;
        }
        __syncthreads();
        if (t < B_) {
            float lo = FINF, hi = -FINF;
#pragma unroll
            for (int j = 0; j < 8; j++) {
                lo = fminf(lo, pmn[t * 8 + j]);
                hi = fmaxf(hi, pmx[t * 8 + j]);
            }
            smn[t] = lo; smx[t] = hi;
        }
        __syncthreads();
        if (t == 0) {
            float a = 0.f, b = 0.f;
            for (int s = 0; s < B_; s++) { a += smn[s]; b += smx[s]; }
            float mn2 = a / 32.f, mx2 = b / 32.f;
            g_mn[2] = mn2;
            g_sc[2] = fmaxf((mx2 - mn2) / QMAX_, 1e-8f);
        }
        __syncthreads();
        float mn2 = g_mn[2], inv2 = 1.f / g_sc[2];
        float Aa = g_A1[t], Cv = g_C1[t];
        for (int i = 0; i < 256; i++) {
            float q1 = mn1 + (float)i * s1;
            float h2 = fmaxf(Aa * q1 + Cv, 0.f);
            float u = (h2 - mn2) * inv2;
            u = fminf(fmaxf(u, 0.f), QMAX_);
            unsigned int b = (unsigned int)(int)rintf(u);
            __nv_bfloat16 bf = __float2bfloat16((float)b);
            unsigned int bits = *reinterpret_cast<unsigned short*>(&bf);
            g_lut32[t * 256 + i] = bits | (b << 16);
        }
    }
}

// Exact-integer pointwise GEMM via mma.sync bf16 (bit-exact: integers <= 255, sums < 2^24).
// Block: 512 thr, tile M=256 x N=128 x K=256 fully smem-resident. B LUT-converted once.
__global__ __launch_bounds__(512) void gemm_kernel(float* __restrict__ out) {
    extern __shared__ char dsm[];
    uint32_t* smAu = reinterpret_cast<uint32_t*>(dsm);
    uint32_t* smBu = reinterpret_cast<uint32_t*>(dsm + SMB_OFF);
    int* sumb = reinterpret_cast<int*>(dsm + SMS_OFF);
    int s = blockIdx.z;
    int pbase = blockIdx.x * GP;
    int tid = threadIdx.x;
    if (tid < GP) sumb[tid] = 0;
    __syncthreads();

    // A copy: 128KB plain bf16 image -> smem with 528B row stride
    {
        const uint2* asrc = reinterpret_cast<const uint2*>(g_aimg16);
#pragma unroll
        for (int j = 0; j < 32; j++) {
            int u = tid + 512 * j;
            int o = u >> 6, cu = u & 63;
            *reinterpret_cast<uint2*>(dsm + o * 528 + cu * 8) = asrc[u];
        }
    }
    // B convert: thread owns pixel p = tid&127, k-pack subset kb + 4j
    {
        int p = tid & 127, kb = tid >> 7;
        int pg = pbase + p;
        if (pg < HW_) {
            const unsigned int* ipk = reinterpret_cast<const unsigned int*>(i_buf) + (size_t)s * 64 * HW_ + pg;
            unsigned int bsum = 0;
#pragma unroll
            for (int j = 0; j < 16; j++) {
                int kk = kb + 4 * j;
                unsigned int w = ipk[(size_t)kk * HW_];
                const unsigned int* lp = g_lut32 + (kk << 10);
                unsigned int e0 = lp[w & 255];
                unsigned int e1 = lp[256 + ((w >> 8) & 255)];
                unsigned int e2 = lp[512 + ((w >> 16) & 255)];
                unsigned int e3 = lp[768 + (w >> 24)];
                *reinterpret_cast<uint2*>(dsm + SMB_OFF + p * 528 + kk * 8) =
                    make_uint2((e0 & 0xFFFFu) | (e1 << 16), (e2 & 0xFFFFu) | (e3 << 16));
                bsum += (e0 >> 16) + (e1 >> 16) + (e2 >> 16) + (e3 >> 16);
            }
            atomicAdd(&sumb[p], (int)bsum);
        } else {
#pragma unroll
            for (int j = 0; j < 16; j++) {
                int kk = kb + 4 * j;
                *reinterpret_cast<uint2*>(dsm + SMB_OFF + p * 528 + kk * 8) = make_uint2(0u, 0u);
            }
        }
    }
    __syncthreads();

    int wid = tid >> 5, lane = tid & 31;
    int wm = wid >> 2, wn = wid & 3;   // 4x4 warp grid: warp tile 64(M) x 32(N)
    int gid = lane >> 2, t4 = lane & 3;

    float acc[4][4][4];
#pragma unroll
    for (int mb = 0; mb < 4; mb++)
#pragma unroll
        for (int nb = 0; nb < 4; nb++)
#pragma unroll
            for (int q = 0; q < 4; q++) acc[mb][nb][q] = 0.f;

    int aoff0[4], boff[4];
#pragma unroll
    for (int mb = 0; mb < 4; mb++) aoff0[mb] = (wm * 64 + mb * 16 + gid) * AW;
#pragma unroll
    for (int nb = 0; nb < 4; nb++) boff[nb] = (wn * 32 + nb * 8 + gid) * AW;

    for (int ks = 0; ks < 16; ks++) {
        int cw = ks * 8 + t4;
        uint32_t af[4][4], bfr[4][2];
#pragma unroll
        for (int mb = 0; mb < 4; mb++) {
            af[mb][0] = smAu[aoff0[mb] + cw];
            af[mb][1] = smAu[aoff0[mb] + 8 * AW + cw];
            af[mb][2] = smAu[aoff0[mb] + cw + 4];
            af[mb][3] = smAu[aoff0[mb] + 8 * AW + cw + 4];
        }
#pragma unroll
        for (int nb = 0; nb < 4; nb++) {
            bfr[nb][0] = smBu[boff[nb] + cw];
            bfr[nb][1] = smBu[boff[nb] + cw + 4];
        }
#pragma unroll
        for (int mb = 0; mb < 4; mb++)
#pragma unroll
            for (int nb = 0; nb < 4; nb++)
                asm volatile(
                    "mma.sync.aligned.m16n8k16.row.col.f32.bf16.bf16.f32 "
                    "{%0,%1,%2,%3}, {%4,%5,%6,%7}, {%8,%9}, {%0,%1,%2,%3};"
                    : "+f"(acc[mb][nb][0]), "+f"(acc[mb][nb][1]),
                      "+f"(acc[mb][nb][2]), "+f"(acc[mb][nb][3])
                    : "r"(af[mb][0]), "r"(af[mb][1]), "r"(af[mb][2]), "r"(af[mb][3]),
                      "r"(bfr[nb][0]), "r"(bfr[nb][1]));
    }

    // Epilogue: affine reconstruction + per-(s,o) min/max
    float wmnv = g_pw_mn, sw = g_pw_sc;
    float mn2 = g_mn[2], s2 = g_sc[2];
    float c0 = sw * s2, cbv = wmnv * s2, ca = mn2 * sw, kc = 256.f * wmnv * mn2;
#pragma unroll
    for (int mb = 0; mb < 4; mb++) {
        int o0 = wm * 64 + mb * 16 + gid, o1 = o0 + 8;
        float base0 = ca * g_suma[o0] + kc;
        float base1 = ca * g_suma[o1] + kc;
        float mn0v = FINF, mx0v = -FINF, mn1v = FINF, mx1v = -FINF;
#pragma unroll
        for (int nb = 0; nb < 4; nb++) {
            int p0 = wn * 32 + nb * 8 + t4 * 2;
            int pg0 = pbase + p0;
            if (pg0 < HW_) {
                float sb0 = (float)sumb[p0], sb1 = (float)sumb[p0 + 1];
                float v00 = c0 * acc[mb][nb][0] + cbv * sb0 + base0;
                float v01 = c0 * acc[mb][nb][1] + cbv * sb1 + base0;
                float v10 = c0 * acc[mb][nb][2] + cbv * sb0 + base1;
                float v11 = c0 * acc[mb][nb][3] + cbv * sb1 + base1;
                *reinterpret_cast<float2*>(out + ((size_t)s * C_ + o0) * HW_ + pg0) = make_float2(v00, v01);
                *reinterpret_cast<float2*>(out + ((size_t)s * C_ + o1) * HW_ + pg0) = make_float2(v10, v11);
                mn0v = fminf(mn0v, fminf(v00, v01)); mx0v = fmaxf(mx0v, fmaxf(v00, v01));
                mn1v = fminf(mn1v, fminf(v10, v11)); mx1v = fmaxf(mx1v, fmaxf(v10, v11));
            }
        }
#pragma unroll
        for (int o2 = 1; o2 <= 2; o2 <<= 1) {
            mn0v = fminf(mn0v, __shfl_xor_sync(0xffffffffu, mn0v, o2));
            mx0v = fmaxf(mx0v, __shfl_xor_sync(0xffffffffu, mx0v, o2));
            mn1v = fminf(mn1v, __shfl_xor_sync(0xffffffffu, mn1v, o2));
            mx1v = fmaxf(mx1v, __shfl_xor_sync(0xffffffffu, mx1v, o2));
        }
        if (t4 == 0) {
            atomicMinF(&g_h3_min[s * C_ + o0], mn0v);
            atomicMaxF(&g_h3_max[s * C_ + o0], mx0v);
            atomicMinF(&g_h3_min[s * C_ + o1], mn1v);
            atomicMaxF(&g_h3_max[s * C_ + o1], mx1v);
        }
    }
}

// Stage1 quantize: read fp32 h3 from out, write u8 indices + per-channel sums.
__global__ __launch_bounds__(256) void quantsum_kernel(const float* __restrict__ ext) {
    int c = blockIdx.x, s = blockIdx.y;
    float mn = g_mn[3], iv = g_inv[3];
    const float4* hp = reinterpret_cast<const float4*>(ext + ((size_t)s * C_ + c) * HW_);
    uchar4* op = reinterpret_cast<uchar4*>(i_buf + ((size_t)s * C_ + c) * HW_);
    int acc = 0;
    for (int p = threadIdx.x; p < HW_ / 4; p += 256) {
        float4 v = hp[p];
        float tx = fminf(fmaxf((v.x - mn) * iv, 0.f), QMAX_);
        float ty = fminf(fmaxf((v.y - mn) * iv, 0.f), QMAX_);
        float tz = fminf(fmaxf((v.z - mn) * iv, 0.f), QMAX_);
        float tw = fminf(fmaxf((v.w - mn) * iv, 0.f), QMAX_);
        int ix = (int)rintf(tx), iy = (int)rintf(ty), iz = (int)rintf(tz), iw = (int)rintf(tw);
        acc += ix + iy + iz + iw;
        op[p] = make_uchar4((unsigned char)ix, (unsigned char)iy, (unsigned char)iz, (unsigned char)iw);
    }
#pragma unroll
    for (int o = 16; o > 0; o >>= 1) acc += __shfl_xor_sync(0xffffffffu, acc, o);
    __shared__ int sd[8];
    int lane = threadIdx.x & 31, wid = threadIdx.x >> 5;
    if (lane == 0) sd[wid] = acc;
    __syncthreads();
    if (threadIdx.x == 0) {
        int tot = 0;
#pragma unroll
        for (int i = 0; i < 8; i++) tot += sd[i];
        atomicAdd(&g_isum2[c], tot);
    }
}

// Final range_bn + relu: read u8 indices, write fp32 out (in place over h3).
__global__ __launch_bounds__(256) void final_kernel(float4* __restrict__ out) {
    const float mn3 = g_mn[3], s3 = g_sc[3];
    const uchar4* ib = reinterpret_cast<const uchar4*>(i_buf);
    size_t stride = (size_t)gridDim.x * blockDim.x;
    for (size_t i = (size_t)blockIdx.x * blockDim.x + threadIdx.x; i < TOT_ / 4; i += stride) {
        int plane = (int)(i / (HW_ / 4));
        int o = plane & 255;
        float A = g_A2[o], Cv = g_C2[o];
        uchar4 q = ib[i];
        float4 v;
        v.x = fmaxf(A * (mn3 + (float)q.x * s3) + Cv, 0.f);
        v.y = fmaxf(A * (mn3 + (float)q.y * s3) + Cv, 0.f);
        v.z = fmaxf(A * (mn3 + (float)q.z * s3) + Cv, 0.f);
        v.w = fmaxf(A * (mn3 + (float)q.w * s3) + Cv, 0.f);
        out[i] = v;
    }
}

extern "C" void kernel_launch(void* const* d_in, const int* in_sizes, int n_in,
                              void* d_out, int out_size) {
    const float* x     = (const float*)d_in[0];
    const float* dw_w  = (const float*)d_in[1];
    const float* dw_b  = (const float*)d_in[2];
    const float* bn1_w = (const float*)d_in[3];
    const float* bn1_b = (const float*)d_in[4];
    const float* pw_w  = (const float*)d_in[5];
    const float* bn2_w = (const float*)d_in[6];
    const float* bn2_b = (const float*)d_in[7];
    float* out = (float*)d_out;

    static int attr_set = 0;
    if (!attr_set) {
        cudaFuncSetAttribute(gemm_kernel, cudaFuncAttributeMaxDynamicSharedMemorySize, SMT_G);
        attr_set = 1;
    }

    init_x_kernel<<<1632, 256>>>(x, pw_w);                    // 0
    prep1_kernel<<<1, 256>>>(dw_w, dw_b, bn1_w, bn2_w, pw_w); // 1
    prep_wbf_kernel<<<256, 256>>>();                          // 2
    conv_kernel<<<dim3(C_, B_), 256>>>(x);                    // 3  <- ncu slot
    prep_stats_kernel<<<1, 256>>>(0);                         // 4
    quantpack_kernel<<<dim3(64, B_), 256>>>();                // 5
    prep_mean_kernel<<<1, 256>>>(0, bn1_b);                   // 6
    gemm_kernel<<<dim3(NPTG, 1, B_), 512, SMT_G>>>(out);      // 7
    prep_stats_kernel<<<1, 256>>>(1);                         // 8
    quantsum_kernel<<<dim3(C_, B_), 256>>>(out);              // 9
    prep_mean_kernel<<<1, 256>>>(1, bn2_b);                   // 10
    final_kernel<<<4096, 256>>>((float4*)out);                // 11
}